// round 1
// baseline (speedup 1.0000x reference)
#include <cuda_runtime.h>

#define B_SZ  1024
#define DHALF 2048
#define DIN   4096
#define DOUT  1024
#define NLAB  128

// Scratch (allocation-free rule: __device__ globals)
__device__ float g_hidden[B_SZ * DOUT];  // relu(hidden)
__device__ float g_emb[B_SZ * DOUT];     // emb

// ---------------------------------------------------------------------------
// Packed f32x2 helpers (FFMA2 path — only reachable via PTX)
// ---------------------------------------------------------------------------
__device__ __forceinline__ unsigned long long pack_dup(float v) {
    unsigned long long r;
    unsigned int u = __float_as_uint(v);
    asm("mov.b64 %0, {%1, %2};" : "=l"(r) : "r"(u), "r"(u));
    return r;
}
__device__ __forceinline__ void ffma2(unsigned long long& acc,
                                      unsigned long long a,
                                      unsigned long long b) {
    asm("fma.rn.f32x2 %0, %1, %2, %0;" : "+l"(acc) : "l"(a), "l"(b));
}

// ---------------------------------------------------------------------------
// Fused GEMM:  C = act( A @ W + bias )
//   MODE 0: A = relu(concat(sbj,obj)) [1024 x 4096], store relu(C) -> g_hidden
//   MODE 1: A = g_hidden              [1024 x 1024], store C       -> g_emb
// Tiles: BM=128, BN=64, BK=16, 256 threads, per-thread 8(M) x 4(N) via f32x2
// Grid: (N/64=16, M/128=8) = 128 CTAs (one full wave).
// ---------------------------------------------------------------------------
#define BM 128
#define BN 64
#define BK 16

template <int MODE>
__global__ __launch_bounds__(256, 2)
void gemm_relu_kernel(const float* __restrict__ sbj,
                      const float* __restrict__ obj,
                      const float* __restrict__ Wmat,
                      const float* __restrict__ bias,
                      float* __restrict__ Cout)
{
    const int K = (MODE == 0) ? DIN : DOUT;
    const int T = K / BK;

    __shared__ float As[2][BK][BM + 2];   // +2 pad: keeps rows 8B aligned, spreads banks
    __shared__ float Bs[2][BK][BN];

    const int tid = threadIdx.x;
    const int m0  = blockIdx.y * BM;
    const int n0  = blockIdx.x * BN;

    const int tx = tid & 15;   // N direction: 4 cols each
    const int ty = tid >> 4;   // M direction: 8 rows each

    // staging registers for the prefetch pipeline
    float4 aReg0, aReg1, bReg;

    // --- global load helpers (register staging) ---
    auto loadG = [&](int t) {
        const int k0 = t * BK;
        // A tile: 128 rows x 16 cols = 512 float4; 2 per thread
        {
            int idx = tid * 2;
            int row = idx >> 2, c4 = idx & 3;
            int gm = m0 + row, gk = k0 + c4 * 4;
            if (MODE == 0) {
                const float* src = (gk < DHALF) ? (sbj + (size_t)gm * DHALF + gk)
                                                : (obj + (size_t)gm * DHALF + (gk - DHALF));
                float4 v = *reinterpret_cast<const float4*>(src);
                v.x = fmaxf(v.x, 0.f); v.y = fmaxf(v.y, 0.f);
                v.z = fmaxf(v.z, 0.f); v.w = fmaxf(v.w, 0.f);
                aReg0 = v;
            } else {
                aReg0 = *reinterpret_cast<const float4*>(&g_hidden[(size_t)gm * DOUT + gk]);
            }
            idx = tid * 2 + 1;
            row = idx >> 2; c4 = idx & 3;
            gm = m0 + row; gk = k0 + c4 * 4;
            if (MODE == 0) {
                const float* src = (gk < DHALF) ? (sbj + (size_t)gm * DHALF + gk)
                                                : (obj + (size_t)gm * DHALF + (gk - DHALF));
                float4 v = *reinterpret_cast<const float4*>(src);
                v.x = fmaxf(v.x, 0.f); v.y = fmaxf(v.y, 0.f);
                v.z = fmaxf(v.z, 0.f); v.w = fmaxf(v.w, 0.f);
                aReg1 = v;
            } else {
                aReg1 = *reinterpret_cast<const float4*>(&g_hidden[(size_t)gm * DOUT + gk]);
            }
        }
        // B tile: 16 rows x 64 cols = 256 float4; 1 per thread
        {
            int kk = tid >> 4, n4 = tid & 15;
            bReg = *reinterpret_cast<const float4*>(&Wmat[(size_t)(k0 + kk) * DOUT + n0 + n4 * 4]);
        }
    };

    auto storeS = [&](int buf) {
        {
            int idx = tid * 2;
            int row = idx >> 2, c4 = idx & 3;
            As[buf][c4 * 4 + 0][row] = aReg0.x;
            As[buf][c4 * 4 + 1][row] = aReg0.y;
            As[buf][c4 * 4 + 2][row] = aReg0.z;
            As[buf][c4 * 4 + 3][row] = aReg0.w;
            idx = tid * 2 + 1;
            row = idx >> 2; c4 = idx & 3;
            As[buf][c4 * 4 + 0][row] = aReg1.x;
            As[buf][c4 * 4 + 1][row] = aReg1.y;
            As[buf][c4 * 4 + 2][row] = aReg1.z;
            As[buf][c4 * 4 + 3][row] = aReg1.w;
        }
        {
            int kk = tid >> 4, n4 = tid & 15;
            *reinterpret_cast<float4*>(&Bs[buf][kk][n4 * 4]) = bReg;
        }
    };

    unsigned long long acc[4][4];
    #pragma unroll
    for (int i = 0; i < 4; i++)
        #pragma unroll
        for (int j = 0; j < 4; j++) acc[i][j] = 0ull;   // {0.0f, 0.0f}

    // prologue
    loadG(0);
    storeS(0);
    __syncthreads();

    for (int t = 0; t < T; t++) {
        const int cur = t & 1;
        const int nxt = cur ^ 1;
        if (t + 1 < T) loadG(t + 1);   // prefetch (latency hidden under compute)

        #pragma unroll
        for (int kk = 0; kk < BK; kk++) {
            unsigned long long apack[4];
            #pragma unroll
            for (int mp = 0; mp < 4; mp++)
                apack[mp] = *reinterpret_cast<const unsigned long long*>(
                    &As[cur][kk][ty * 8 + mp * 2]);
            float4 bv = *reinterpret_cast<const float4*>(&Bs[cur][kk][tx * 4]);
            unsigned long long bp0 = pack_dup(bv.x);
            unsigned long long bp1 = pack_dup(bv.y);
            unsigned long long bp2 = pack_dup(bv.z);
            unsigned long long bp3 = pack_dup(bv.w);
            #pragma unroll
            for (int mp = 0; mp < 4; mp++) {
                ffma2(acc[mp][0], apack[mp], bp0);
                ffma2(acc[mp][1], apack[mp], bp1);
                ffma2(acc[mp][2], apack[mp], bp2);
                ffma2(acc[mp][3], apack[mp], bp3);
            }
        }

        if (t + 1 < T) storeS(nxt);
        __syncthreads();
    }

    // epilogue: bias (+ relu for MODE 0), write out
    #pragma unroll
    for (int n = 0; n < 4; n++) {
        const int col = n0 + tx * 4 + n;
        const float bb = bias[col];
        #pragma unroll
        for (int mp = 0; mp < 4; mp++) {
            float2 v = *reinterpret_cast<float2*>(&acc[mp][n]);
            const int r0 = m0 + ty * 8 + mp * 2;
            float o0 = v.x + bb;
            float o1 = v.y + bb;
            if (MODE == 0) { o0 = fmaxf(o0, 0.f); o1 = fmaxf(o1, 0.f); }
            Cout[(size_t)r0 * DOUT + col]       = o0;
            Cout[(size_t)(r0 + 1) * DOUT + col] = o1;
        }
    }
}

// ---------------------------------------------------------------------------
// Scores: out[b,l] = -sqrt( sum_d relu(label[l,d] - emb[b,d])^2 )
// Block: 8 b-rows x all 128 labels; k chunked by 64 with both operands in smem.
// 256 threads: l = tid&127, bg = tid>>7 -> each thread does 4 b-rows.
// Grid: 1024/8 = 128 CTAs (one wave).
// Ls padded to 65 (odd) so Ls[l][k] with consecutive l is bank-conflict-free.
// ---------------------------------------------------------------------------
__global__ __launch_bounds__(256)
void scores_kernel(const float* __restrict__ labels, float* __restrict__ out)
{
    __shared__ float Ls[NLAB][65];
    __shared__ float Es[8][65];

    const int tid = threadIdx.x;
    const int b0  = blockIdx.x * 8;
    const int l   = tid & 127;
    const int bg  = tid >> 7;     // 0 or 1

    float acc0 = 0.f, acc1 = 0.f, acc2 = 0.f, acc3 = 0.f;

    for (int k0 = 0; k0 < DOUT; k0 += 64) {
        // labels chunk: 128 x 64 = 2048 float4-quarters -> 8 float4 per thread
        #pragma unroll
        for (int j = 0; j < 8; j++) {
            int idx = tid + j * 256;        // 0..2047
            int row = idx >> 4;             // 0..127
            int c4  = idx & 15;
            float4 v = *reinterpret_cast<const float4*>(
                &labels[(size_t)row * DOUT + k0 + c4 * 4]);
            Ls[row][c4 * 4 + 0] = v.x;
            Ls[row][c4 * 4 + 1] = v.y;
            Ls[row][c4 * 4 + 2] = v.z;
            Ls[row][c4 * 4 + 3] = v.w;
        }
        // emb chunk: 8 x 64 = 128 float4
        if (tid < 128) {
            int row = tid >> 4, c4 = tid & 15;
            float4 v = *reinterpret_cast<const float4*>(
                &g_emb[(size_t)(b0 + row) * DOUT + k0 + c4 * 4]);
            Es[row][c4 * 4 + 0] = v.x;
            Es[row][c4 * 4 + 1] = v.y;
            Es[row][c4 * 4 + 2] = v.z;
            Es[row][c4 * 4 + 3] = v.w;
        }
        __syncthreads();

        #pragma unroll 4
        for (int k = 0; k < 64; k++) {
            const float lk = Ls[l][k];
            float d0 = fmaxf(lk - Es[bg * 4 + 0][k], 0.f);
            float d1 = fmaxf(lk - Es[bg * 4 + 1][k], 0.f);
            float d2 = fmaxf(lk - Es[bg * 4 + 2][k], 0.f);
            float d3 = fmaxf(lk - Es[bg * 4 + 3][k], 0.f);
            acc0 = fmaf(d0, d0, acc0);
            acc1 = fmaf(d1, d1, acc1);
            acc2 = fmaf(d2, d2, acc2);
            acc3 = fmaf(d3, d3, acc3);
        }
        __syncthreads();
    }

    out[(size_t)(b0 + bg * 4 + 0) * NLAB + l] = -sqrtf(acc0);
    out[(size_t)(b0 + bg * 4 + 1) * NLAB + l] = -sqrtf(acc1);
    out[(size_t)(b0 + bg * 4 + 2) * NLAB + l] = -sqrtf(acc2);
    out[(size_t)(b0 + bg * 4 + 3) * NLAB + l] = -sqrtf(acc3);
}

// ---------------------------------------------------------------------------
// Launch
// ---------------------------------------------------------------------------
extern "C" void kernel_launch(void* const* d_in, const int* in_sizes, int n_in,
                              void* d_out, int out_size)
{
    const float* sbj    = (const float*)d_in[0];  // [1024, 2048]
    const float* obj    = (const float*)d_in[1];  // [1024, 2048]
    const float* W1     = (const float*)d_in[2];  // [4096, 1024]
    const float* b1     = (const float*)d_in[3];  // [1024]
    const float* W2     = (const float*)d_in[4];  // [1024, 1024]
    const float* b2     = (const float*)d_in[5];  // [1024]
    const float* labels = (const float*)d_in[6];  // [128, 1024]
    float* out = (float*)d_out;                   // [1024, 128]

    float* hidden_ptr;
    float* emb_ptr;
    cudaGetSymbolAddress((void**)&hidden_ptr, g_hidden);
    cudaGetSymbolAddress((void**)&emb_ptr, g_emb);

    dim3 gemm_grid(DOUT / BN, B_SZ / BM);   // (16, 8) = 128 CTAs
    gemm_relu_kernel<0><<<gemm_grid, 256>>>(sbj, obj, W1, b1, hidden_ptr);
    gemm_relu_kernel<1><<<gemm_grid, 256>>>(sbj, obj, W2, b2, emb_ptr);
    scores_kernel<<<B_SZ / 8, 256>>>(labels, out);
}

// round 2
// speedup vs baseline: 1.4182x; 1.4182x over previous
#include <cuda_runtime.h>
#include <cstdint>

#define B_SZ  1024
#define DHALF 2048
#define DIN   4096
#define DOUT  1024
#define NLAB  128

// Scratch (allocation-free rule: __device__ globals)
__device__ float g_hidden[B_SZ * DOUT];  // relu(hidden)
__device__ float g_emb[B_SZ * DOUT];     // emb

// ---------------------------------------------------------------------------
// tf32 helpers
// ---------------------------------------------------------------------------
__device__ __forceinline__ float f2tf32(float x) {
    uint32_t r;
    asm("cvt.rna.tf32.f32 %0, %1;" : "=r"(r) : "f"(x));
    return __uint_as_float(r);
}

__device__ __forceinline__ void mma_tf32(float& c0, float& c1, float& c2, float& c3,
                                         uint32_t a0, uint32_t a1, uint32_t a2, uint32_t a3,
                                         uint32_t b0, uint32_t b1) {
    asm volatile(
        "mma.sync.aligned.m16n8k8.row.col.f32.tf32.tf32.f32 "
        "{%0,%1,%2,%3}, {%4,%5,%6,%7}, {%8,%9}, {%0,%1,%2,%3};"
        : "+f"(c0), "+f"(c1), "+f"(c2), "+f"(c3)
        : "r"(a0), "r"(a1), "r"(a2), "r"(a3), "r"(b0), "r"(b1));
}

// ---------------------------------------------------------------------------
// tf32 tensor-core GEMM:  C = act( A @ W + bias )
//   MODE 0: A = relu(concat(sbj,obj)) [1024 x 4096], store relu(C) -> g_hidden
//   MODE 1: A = g_hidden              [1024 x 1024], store C       -> g_emb
// Tiles: BM=128, BN=64, BK=16. 256 threads = 8 warps in 4(M) x 2(N) grid,
// warp tile 32x32 = 2(m16) x 4(n8) mma fragments per k8 step.
// Grid: (1024/64, 1024/128) = (16, 8) = 128 CTAs (one full wave).
// smem bank analysis:
//   As[m][k] stride 20 : a-frag lanes hit (l4*20 + lq) -> 20g mod 32 covers
//                        {0,20,8,28,16,4,24,12} -> 8 disjoint 4-banks. clean.
//   Bs[k][n] stride 72 : b-frag lanes hit (lq*72 + l4) -> 8lq + l4 = 0..31. clean.
// ---------------------------------------------------------------------------
#define BM 128
#define BN 64
#define BK 16

#define AS_STRIDE 20
#define BS_STRIDE 72

template <int MODE>
__global__ __launch_bounds__(256)
void gemm_tf32_kernel(const float* __restrict__ sbj,
                      const float* __restrict__ obj,
                      const float* __restrict__ Wmat,
                      const float* __restrict__ bias,
                      float* __restrict__ Cout)
{
    const int K = (MODE == 0) ? DIN : DOUT;
    const int T = K / BK;

    __shared__ float As[2][BM][AS_STRIDE];  // 2*128*20*4 = 20480 B
    __shared__ float Bs[2][BK][BS_STRIDE];  // 2*16*72*4  =  9216 B

    const int tid  = threadIdx.x;
    const int wid  = tid >> 5;
    const int lane = tid & 31;
    const int lq   = lane & 3;   // quad col
    const int l4   = lane >> 2;  // quad row

    const int m0 = blockIdx.y * BM;
    const int n0 = blockIdx.x * BN;
    const int wm = (wid >> 1) * 32;  // warp m offset in tile
    const int wn = (wid & 1) * 32;   // warp n offset in tile

    // prefetch staging registers
    float4 aReg0, aReg1, bReg;

    auto loadG = [&](int t) {
        const int k0 = t * BK;
        // A tile: 128 rows x 16 k = 512 float4, 2 per thread
        {
            int idx = tid * 2;
            int row = idx >> 2, c4 = idx & 3;
            int gm = m0 + row, gk = k0 + c4 * 4;
            if (MODE == 0) {
                const float* src = (gk < DHALF) ? (sbj + (size_t)gm * DHALF + gk)
                                                : (obj + (size_t)gm * DHALF + (gk - DHALF));
                float4 v = *reinterpret_cast<const float4*>(src);
                v.x = fmaxf(v.x, 0.f); v.y = fmaxf(v.y, 0.f);
                v.z = fmaxf(v.z, 0.f); v.w = fmaxf(v.w, 0.f);
                aReg0 = v;
            } else {
                aReg0 = *reinterpret_cast<const float4*>(&g_hidden[(size_t)gm * DOUT + gk]);
            }
            idx = tid * 2 + 1;
            row = idx >> 2; c4 = idx & 3;
            gm = m0 + row; gk = k0 + c4 * 4;
            if (MODE == 0) {
                const float* src = (gk < DHALF) ? (sbj + (size_t)gm * DHALF + gk)
                                                : (obj + (size_t)gm * DHALF + (gk - DHALF));
                float4 v = *reinterpret_cast<const float4*>(src);
                v.x = fmaxf(v.x, 0.f); v.y = fmaxf(v.y, 0.f);
                v.z = fmaxf(v.z, 0.f); v.w = fmaxf(v.w, 0.f);
                aReg1 = v;
            } else {
                aReg1 = *reinterpret_cast<const float4*>(&g_hidden[(size_t)gm * DOUT + gk]);
            }
        }
        // B tile: 16 k x 64 n = 256 float4, 1 per thread
        {
            int kk = tid >> 4, n4 = tid & 15;
            bReg = *reinterpret_cast<const float4*>(
                &Wmat[(size_t)(k0 + kk) * DOUT + n0 + n4 * 4]);
        }
    };

    auto storeS = [&](int buf) {
        {
            int idx = tid * 2;
            int row = idx >> 2, c4 = idx & 3;
            float4 v;
            v.x = f2tf32(aReg0.x); v.y = f2tf32(aReg0.y);
            v.z = f2tf32(aReg0.z); v.w = f2tf32(aReg0.w);
            *reinterpret_cast<float4*>(&As[buf][row][c4 * 4]) = v;
            idx = tid * 2 + 1;
            row = idx >> 2; c4 = idx & 3;
            v.x = f2tf32(aReg1.x); v.y = f2tf32(aReg1.y);
            v.z = f2tf32(aReg1.z); v.w = f2tf32(aReg1.w);
            *reinterpret_cast<float4*>(&As[buf][row][c4 * 4]) = v;
        }
        {
            int kk = tid >> 4, n4 = tid & 15;
            float4 v;
            v.x = f2tf32(bReg.x); v.y = f2tf32(bReg.y);
            v.z = f2tf32(bReg.z); v.w = f2tf32(bReg.w);
            *reinterpret_cast<float4*>(&Bs[buf][kk][n4 * 4]) = v;
        }
    };

    float acc[2][4][4];
    #pragma unroll
    for (int mi = 0; mi < 2; mi++)
        #pragma unroll
        for (int nj = 0; nj < 4; nj++)
            #pragma unroll
            for (int r = 0; r < 4; r++) acc[mi][nj][r] = 0.f;

    loadG(0);
    storeS(0);
    __syncthreads();

    for (int t = 0; t < T; t++) {
        const int cur = t & 1;
        const int nxt = cur ^ 1;
        if (t + 1 < T) loadG(t + 1);

        #pragma unroll
        for (int k8 = 0; k8 < BK; k8 += 8) {
            uint32_t a[2][4];
            #pragma unroll
            for (int mi = 0; mi < 2; mi++) {
                const int R = wm + mi * 16 + l4;
                a[mi][0] = __float_as_uint(As[cur][R][k8 + lq]);
                a[mi][1] = __float_as_uint(As[cur][R + 8][k8 + lq]);
                a[mi][2] = __float_as_uint(As[cur][R][k8 + lq + 4]);
                a[mi][3] = __float_as_uint(As[cur][R + 8][k8 + lq + 4]);
            }
            uint32_t b[4][2];
            #pragma unroll
            for (int nj = 0; nj < 4; nj++) {
                const int Cn = wn + nj * 8 + l4;
                b[nj][0] = __float_as_uint(Bs[cur][k8 + lq][Cn]);
                b[nj][1] = __float_as_uint(Bs[cur][k8 + lq + 4][Cn]);
            }
            #pragma unroll
            for (int mi = 0; mi < 2; mi++)
                #pragma unroll
                for (int nj = 0; nj < 4; nj++)
                    mma_tf32(acc[mi][nj][0], acc[mi][nj][1],
                             acc[mi][nj][2], acc[mi][nj][3],
                             a[mi][0], a[mi][1], a[mi][2], a[mi][3],
                             b[nj][0], b[nj][1]);
        }

        if (t + 1 < T) storeS(nxt);
        __syncthreads();
    }

    // epilogue: bias (+relu for MODE 0); c0,c1 at (row, col..col+1), c2,c3 at row+8
    #pragma unroll
    for (int nj = 0; nj < 4; nj++) {
        const int col = n0 + wn + nj * 8 + lq * 2;
        const float bb0 = bias[col];
        const float bb1 = bias[col + 1];
        #pragma unroll
        for (int mi = 0; mi < 2; mi++) {
            const int row = m0 + wm + mi * 16 + l4;
            float o0 = acc[mi][nj][0] + bb0;
            float o1 = acc[mi][nj][1] + bb1;
            float o2 = acc[mi][nj][2] + bb0;
            float o3 = acc[mi][nj][3] + bb1;
            if (MODE == 0) {
                o0 = fmaxf(o0, 0.f); o1 = fmaxf(o1, 0.f);
                o2 = fmaxf(o2, 0.f); o3 = fmaxf(o3, 0.f);
            }
            float2 p0 = {o0, o1};
            float2 p1 = {o2, o3};
            *reinterpret_cast<float2*>(&Cout[(size_t)row * DOUT + col])       = p0;
            *reinterpret_cast<float2*>(&Cout[(size_t)(row + 8) * DOUT + col]) = p1;
        }
    }
}

// ---------------------------------------------------------------------------
// Scores: out[b,l] = -sqrt( sum_d relu(label[l,d] - emb[b,d])^2 )
// Block: 8 b-rows x all 128 labels; k chunked by 64 with both operands in smem.
// ---------------------------------------------------------------------------
__global__ __launch_bounds__(256)
void scores_kernel(const float* __restrict__ labels, float* __restrict__ out)
{
    __shared__ float Ls[NLAB][65];
    __shared__ float Es[8][65];

    const int tid = threadIdx.x;
    const int b0  = blockIdx.x * 8;
    const int l   = tid & 127;
    const int bg  = tid >> 7;     // 0 or 1

    float acc0 = 0.f, acc1 = 0.f, acc2 = 0.f, acc3 = 0.f;

    for (int k0 = 0; k0 < DOUT; k0 += 64) {
        #pragma unroll
        for (int j = 0; j < 8; j++) {
            int idx = tid + j * 256;        // 0..2047
            int row = idx >> 4;             // 0..127
            int c4  = idx & 15;
            float4 v = *reinterpret_cast<const float4*>(
                &labels[(size_t)row * DOUT + k0 + c4 * 4]);
            Ls[row][c4 * 4 + 0] = v.x;
            Ls[row][c4 * 4 + 1] = v.y;
            Ls[row][c4 * 4 + 2] = v.z;
            Ls[row][c4 * 4 + 3] = v.w;
        }
        if (tid < 128) {
            int row = tid >> 4, c4 = tid & 15;
            float4 v = *reinterpret_cast<const float4*>(
                &g_emb[(size_t)(b0 + row) * DOUT + k0 + c4 * 4]);
            Es[row][c4 * 4 + 0] = v.x;
            Es[row][c4 * 4 + 1] = v.y;
            Es[row][c4 * 4 + 2] = v.z;
            Es[row][c4 * 4 + 3] = v.w;
        }
        __syncthreads();

        #pragma unroll 4
        for (int k = 0; k < 64; k++) {
            const float lk = Ls[l][k];
            float d0 = fmaxf(lk - Es[bg * 4 + 0][k], 0.f);
            float d1 = fmaxf(lk - Es[bg * 4 + 1][k], 0.f);
            float d2 = fmaxf(lk - Es[bg * 4 + 2][k], 0.f);
            float d3 = fmaxf(lk - Es[bg * 4 + 3][k], 0.f);
            acc0 = fmaf(d0, d0, acc0);
            acc1 = fmaf(d1, d1, acc1);
            acc2 = fmaf(d2, d2, acc2);
            acc3 = fmaf(d3, d3, acc3);
        }
        __syncthreads();
    }

    out[(size_t)(b0 + bg * 4 + 0) * NLAB + l] = -sqrtf(acc0);
    out[(size_t)(b0 + bg * 4 + 1) * NLAB + l] = -sqrtf(acc1);
    out[(size_t)(b0 + bg * 4 + 2) * NLAB + l] = -sqrtf(acc2);
    out[(size_t)(b0 + bg * 4 + 3) * NLAB + l] = -sqrtf(acc3);
}

// ---------------------------------------------------------------------------
// Launch
// ---------------------------------------------------------------------------
extern "C" void kernel_launch(void* const* d_in, const int* in_sizes, int n_in,
                              void* d_out, int out_size)
{
    const float* sbj    = (const float*)d_in[0];  // [1024, 2048]
    const float* obj    = (const float*)d_in[1];  // [1024, 2048]
    const float* W1     = (const float*)d_in[2];  // [4096, 1024]
    const float* b1     = (const float*)d_in[3];  // [1024]
    const float* W2     = (const float*)d_in[4];  // [1024, 1024]
    const float* b2     = (const float*)d_in[5];  // [1024]
    const float* labels = (const float*)d_in[6];  // [128, 1024]
    float* out = (float*)d_out;                   // [1024, 128]

    float* hidden_ptr;
    float* emb_ptr;
    cudaGetSymbolAddress((void**)&hidden_ptr, g_hidden);
    cudaGetSymbolAddress((void**)&emb_ptr, g_emb);

    dim3 gemm_grid(DOUT / BN, B_SZ / BM);   // (16, 8) = 128 CTAs
    gemm_tf32_kernel<0><<<gemm_grid, 256>>>(sbj, obj, W1, b1, hidden_ptr);
    gemm_tf32_kernel<1><<<gemm_grid, 256>>>(sbj, obj, W2, b2, emb_ptr);
    scores_kernel<<<B_SZ / 8, 256>>>(labels, out);
}

// round 4
// speedup vs baseline: 1.9950x; 1.4067x over previous
#include <cuda_runtime.h>
#include <cstdint>

#define B_SZ  1024
#define DHALF 2048
#define DIN   4096
#define DOUT  1024
#define NLAB  128

// Scratch (allocation-free rule: __device__ globals)
__device__ float g_hidden[B_SZ * DOUT];  // relu(hidden)
__device__ float g_emb[B_SZ * DOUT];     // emb

// ---------------------------------------------------------------------------
// helpers
// ---------------------------------------------------------------------------
__device__ __forceinline__ uint32_t smem_u32(const void* p) {
    uint32_t a;
    asm("{ .reg .u64 t; cvta.to.shared.u64 t, %1; cvt.u32.u64 %0, t; }"
        : "=r"(a) : "l"(p));
    return a;
}
#define CP16(dst, src) asm volatile("cp.async.cg.shared.global [%0], [%1], 16;" :: "r"(dst), "l"(src) : "memory")
#define CP_COMMIT()    asm volatile("cp.async.commit_group;" ::: "memory")

__device__ __forceinline__ void mma_tf32(float& c0, float& c1, float& c2, float& c3,
                                         uint32_t a0, uint32_t a1, uint32_t a2, uint32_t a3,
                                         uint32_t b0, uint32_t b1) {
    asm volatile(
        "mma.sync.aligned.m16n8k8.row.col.f32.tf32.tf32.f32 "
        "{%0,%1,%2,%3}, {%4,%5,%6,%7}, {%8,%9}, {%0,%1,%2,%3};"
        : "+f"(c0), "+f"(c1), "+f"(c2), "+f"(c3)
        : "r"(a0), "r"(a1), "r"(a2), "r"(a3), "r"(b0), "r"(b1));
}

// ---------------------------------------------------------------------------
// tf32 tensor GEMM: C = act(A @ W + bias)
//   MODE 0: A = relu(concat(sbj,obj)) [1024x4096] -> relu(C) to g_hidden
//   MODE 1: A = g_hidden              [1024x1024] -> C to g_emb
// BM=BN=64, BK=32. 256 thr = 8 warps, warp tile 16(m) x 32(n) = 4 n8-frags.
// Grid (16,16) = 256 CTAs; __launch_bounds__(256,2) -> 2 CTAs/SM, 16 warps/SM.
// Double-buffered smem, B (and A in MODE 1) via cp.async; A in MODE 0 via
// LDG+relu+STS with loads hoisted above the wait.
// Bank-clean strides: As[m][k] stride 36 (4*l4+lq perm), Bs[k][n] stride 72
// (8*lq+l4 perm). Raw fp32 bits fed to HMMA.tf32 (HW truncates mantissa).
// ---------------------------------------------------------------------------
#define BM 64
#define BN 64
#define BK 32
#define AS_STR 36
#define BS_STR 72

template <int MODE>
__global__ __launch_bounds__(256, 2)
void gemm_tf32_kernel(const float* __restrict__ sbj,
                      const float* __restrict__ obj,
                      const float* __restrict__ Wmat,
                      const float* __restrict__ bias,
                      float* __restrict__ Cout)
{
    const int K = (MODE == 0) ? DIN : DOUT;
    const int T = K / BK;

    __shared__ float As[2][BM][AS_STR];  // 2*64*36*4 = 18432 B
    __shared__ float Bs[2][BK][BS_STR];  // 2*32*72*4 = 18432 B

    const int tid  = threadIdx.x;
    const int wid  = tid >> 5;
    const int lane = tid & 31;
    const int lq   = lane & 3;
    const int l4   = lane >> 2;

    const int m0 = blockIdx.y * BM;
    const int n0 = blockIdx.x * BN;
    const int wm = (wid & 3) * 16;   // warp m offset (4 tiles)
    const int wn = (wid >> 2) * 32;  // warp n offset (2 tiles)

    // load indexing: A tile 64r x 8 float4; B tile 32r x 16 float4; 2 each
    const int ar0 = tid >> 3,        ac = tid & 7;        // + (tid+256)>>3
    const int ar1 = (tid + 256) >> 3;
    const int br0 = tid >> 4,        bc = tid & 15;
    const int br1 = (tid + 256) >> 4;

    // precomputed smem byte addresses for cp.async destinations
    uint32_t bsd0[2], bsd1[2], asd0[2], asd1[2];
    #pragma unroll
    for (int b = 0; b < 2; b++) {
        bsd0[b] = smem_u32(&Bs[b][br0][bc * 4]);
        bsd1[b] = smem_u32(&Bs[b][br1][bc * 4]);
        asd0[b] = smem_u32(&As[b][ar0][ac * 4]);
        asd1[b] = smem_u32(&As[b][ar1][ac * 4]);
    }

    auto issueLoads = [&](int t, int buf, float4* av) {
        const int k0 = t * BK;
        // B via cp.async
        CP16(bsd0[buf], &Wmat[(size_t)(k0 + br0) * DOUT + n0 + bc * 4]);
        CP16(bsd1[buf], &Wmat[(size_t)(k0 + br1) * DOUT + n0 + bc * 4]);
        if (MODE == 0) {
            // A via LDG + relu (stage is wholly in sbj or obj: DHALF % BK == 0)
            const float* base = (k0 < DHALF) ? sbj : obj;
            const int kk = (k0 < DHALF) ? k0 : (k0 - DHALF);
            float4 v0 = *reinterpret_cast<const float4*>(
                &base[(size_t)(m0 + ar0) * DHALF + kk + ac * 4]);
            float4 v1 = *reinterpret_cast<const float4*>(
                &base[(size_t)(m0 + ar1) * DHALF + kk + ac * 4]);
            v0.x = fmaxf(v0.x, 0.f); v0.y = fmaxf(v0.y, 0.f);
            v0.z = fmaxf(v0.z, 0.f); v0.w = fmaxf(v0.w, 0.f);
            v1.x = fmaxf(v1.x, 0.f); v1.y = fmaxf(v1.y, 0.f);
            v1.z = fmaxf(v1.z, 0.f); v1.w = fmaxf(v1.w, 0.f);
            av[0] = v0; av[1] = v1;
        } else {
            CP16(asd0[buf], &g_hidden[(size_t)(m0 + ar0) * DOUT + k0 + ac * 4]);
            CP16(asd1[buf], &g_hidden[(size_t)(m0 + ar1) * DOUT + k0 + ac * 4]);
        }
        CP_COMMIT();
    };
    auto storeA = [&](int buf, const float4* av) {
        *reinterpret_cast<float4*>(&As[buf][ar0][ac * 4]) = av[0];
        *reinterpret_cast<float4*>(&As[buf][ar1][ac * 4]) = av[1];
    };

    float acc[4][4];
    #pragma unroll
    for (int nj = 0; nj < 4; nj++)
        #pragma unroll
        for (int r = 0; r < 4; r++) acc[nj][r] = 0.f;

    // prologue: stage 0 -> buffer 0
    {
        float4 av[2];
        issueLoads(0, 0, av);
        if (MODE == 0) storeA(0, av);
    }

    for (int t = 0; t < T; t++) {
        const int cur = t & 1;
        const int nxt = cur ^ 1;
        const bool pf = (t + 1 < T);

        float4 av[2];
        if (pf) issueLoads(t + 1, nxt, av);

        if (pf) asm volatile("cp.async.wait_group 1;" ::: "memory");
        else    asm volatile("cp.async.wait_group 0;" ::: "memory");
        __syncthreads();

        #pragma unroll
        for (int k8 = 0; k8 < BK; k8 += 8) {
            uint32_t a0, a1, a2, a3;
            const int R = wm + l4;
            a0 = __float_as_uint(As[cur][R][k8 + lq]);
            a1 = __float_as_uint(As[cur][R + 8][k8 + lq]);
            a2 = __float_as_uint(As[cur][R][k8 + lq + 4]);
            a3 = __float_as_uint(As[cur][R + 8][k8 + lq + 4]);
            uint32_t b[4][2];
            #pragma unroll
            for (int nj = 0; nj < 4; nj++) {
                const int Cn = wn + nj * 8 + l4;
                b[nj][0] = __float_as_uint(Bs[cur][k8 + lq][Cn]);
                b[nj][1] = __float_as_uint(Bs[cur][k8 + lq + 4][Cn]);
            }
            #pragma unroll
            for (int nj = 0; nj < 4; nj++)
                mma_tf32(acc[nj][0], acc[nj][1], acc[nj][2], acc[nj][3],
                         a0, a1, a2, a3, b[nj][0], b[nj][1]);
        }

        if (pf && MODE == 0) storeA(nxt, av);
        __syncthreads();
    }

    // epilogue: bias (+relu MODE 0)
    #pragma unroll
    for (int nj = 0; nj < 4; nj++) {
        const int col = n0 + wn + nj * 8 + lq * 2;
        const float bb0 = bias[col];
        const float bb1 = bias[col + 1];
        const int row = m0 + wm + l4;
        float o0 = acc[nj][0] + bb0;
        float o1 = acc[nj][1] + bb1;
        float o2 = acc[nj][2] + bb0;
        float o3 = acc[nj][3] + bb1;
        if (MODE == 0) {
            o0 = fmaxf(o0, 0.f); o1 = fmaxf(o1, 0.f);
            o2 = fmaxf(o2, 0.f); o3 = fmaxf(o3, 0.f);
        }
        float2 p0 = {o0, o1};
        float2 p1 = {o2, o3};
        *reinterpret_cast<float2*>(&Cout[(size_t)row * DOUT + col])       = p0;
        *reinterpret_cast<float2*>(&Cout[(size_t)(row + 8) * DOUT + col]) = p1;
    }
}

// ---------------------------------------------------------------------------
// Scores: out[b,l] = -sqrt( sum_d relu(label[l,d] - emb[b,d])^2 )
// ---------------------------------------------------------------------------
__global__ __launch_bounds__(256)
void scores_kernel(const float* __restrict__ labels, float* __restrict__ out)
{
    __shared__ float Ls[NLAB][65];
    __shared__ float Es[8][65];

    const int tid = threadIdx.x;
    const int b0  = blockIdx.x * 8;
    const int l   = tid & 127;
    const int bg  = tid >> 7;

    float acc0 = 0.f, acc1 = 0.f, acc2 = 0.f, acc3 = 0.f;

    for (int k0 = 0; k0 < DOUT; k0 += 64) {
        #pragma unroll
        for (int j = 0; j < 8; j++) {
            int idx = tid + j * 256;
            int row = idx >> 4;
            int c4  = idx & 15;
            float4 v = *reinterpret_cast<const float4*>(
                &labels[(size_t)row * DOUT + k0 + c4 * 4]);
            Ls[row][c4 * 4 + 0] = v.x;
            Ls[row][c4 * 4 + 1] = v.y;
            Ls[row][c4 * 4 + 2] = v.z;
            Ls[row][c4 * 4 + 3] = v.w;
        }
        if (tid < 128) {
            int row = tid >> 4, c4 = tid & 15;
            float4 v = *reinterpret_cast<const float4*>(
                &g_emb[(size_t)(b0 + row) * DOUT + k0 + c4 * 4]);
            Es[row][c4 * 4 + 0] = v.x;
            Es[row][c4 * 4 + 1] = v.y;
            Es[row][c4 * 4 + 2] = v.z;
            Es[row][c4 * 4 + 3] = v.w;
        }
        __syncthreads();

        #pragma unroll 4
        for (int k = 0; k < 64; k++) {
            const float lk = Ls[l][k];
            float d0 = fmaxf(lk - Es[bg * 4 + 0][k], 0.f);
            float d1 = fmaxf(lk - Es[bg * 4 + 1][k], 0.f);
            float d2 = fmaxf(lk - Es[bg * 4 + 2][k], 0.f);
            float d3 = fmaxf(lk - Es[bg * 4 + 3][k], 0.f);
            acc0 = fmaf(d0, d0, acc0);
            acc1 = fmaf(d1, d1, acc1);
            acc2 = fmaf(d2, d2, acc2);
            acc3 = fmaf(d3, d3, acc3);
        }
        __syncthreads();
    }

    out[(size_t)(b0 + bg * 4 + 0) * NLAB + l] = -sqrtf(acc0);
    out[(size_t)(b0 + bg * 4 + 1) * NLAB + l] = -sqrtf(acc1);
    out[(size_t)(b0 + bg * 4 + 2) * NLAB + l] = -sqrtf(acc2);
    out[(size_t)(b0 + bg * 4 + 3) * NLAB + l] = -sqrtf(acc3);
}

// ---------------------------------------------------------------------------
// Launch
// ---------------------------------------------------------------------------
extern "C" void kernel_launch(void* const* d_in, const int* in_sizes, int n_in,
                              void* d_out, int out_size)
{
    const float* sbj    = (const float*)d_in[0];
    const float* obj    = (const float*)d_in[1];
    const float* W1     = (const float*)d_in[2];
    const float* b1     = (const float*)d_in[3];
    const float* W2     = (const float*)d_in[4];
    const float* b2     = (const float*)d_in[5];
    const float* labels = (const float*)d_in[6];
    float* out = (float*)d_out;

    float *hidden_ptr, *emb_ptr;
    cudaGetSymbolAddress((void**)&hidden_ptr, g_hidden);
    cudaGetSymbolAddress((void**)&emb_ptr, g_emb);

    dim3 grid(DOUT / BN, B_SZ / BM);   // (16,16) = 256 CTAs
    gemm_tf32_kernel<0><<<grid, 256>>>(sbj, obj, W1, b1, hidden_ptr);
    gemm_tf32_kernel<1><<<grid, 256>>>(sbj, obj, W2, b2, emb_ptr);
    scores_kernel<<<B_SZ / 8, 256>>>(labels, out);
}

// round 5
// speedup vs baseline: 2.1736x; 1.0895x over previous
#include <cuda_runtime.h>
#include <cstdint>

#define B_SZ  1024
#define DHALF 2048
#define DIN   4096
#define DOUT  1024
#define NLAB  128

// Scratch (allocation-free rule: __device__ globals)
__device__ float g_x[B_SZ * DIN];        // relu(concat(sbj,obj))
__device__ float g_hidden[B_SZ * DOUT];  // relu(hidden)
__device__ float g_emb[B_SZ * DOUT];     // emb

// ---------------------------------------------------------------------------
// helpers
// ---------------------------------------------------------------------------
__device__ __forceinline__ uint32_t smem_u32(const void* p) {
    uint32_t a;
    asm("{ .reg .u64 t; cvta.to.shared.u64 t, %1; cvt.u32.u64 %0, t; }"
        : "=r"(a) : "l"(p));
    return a;
}
#define CP16(dst, src) asm volatile("cp.async.cg.shared.global [%0], [%1], 16;" :: "r"(dst), "l"(src) : "memory")
#define CP_COMMIT()    asm volatile("cp.async.commit_group;" ::: "memory")

__device__ __forceinline__ void mma_tf32(float& c0, float& c1, float& c2, float& c3,
                                         uint32_t a0, uint32_t a1, uint32_t a2, uint32_t a3,
                                         uint32_t b0, uint32_t b1) {
    asm volatile(
        "mma.sync.aligned.m16n8k8.row.col.f32.tf32.tf32.f32 "
        "{%0,%1,%2,%3}, {%4,%5,%6,%7}, {%8,%9}, {%0,%1,%2,%3};"
        : "+f"(c0), "+f"(c1), "+f"(c2), "+f"(c3)
        : "r"(a0), "r"(a1), "r"(a2), "r"(a3), "r"(b0), "r"(b1));
}

// ---------------------------------------------------------------------------
// Prepass: g_x[m][k] = relu(concat(sbj,obj))  (pure bandwidth, ~6us)
// ---------------------------------------------------------------------------
__global__ __launch_bounds__(256)
void relu_cat_kernel(const float* __restrict__ sbj, const float* __restrict__ obj,
                     float* __restrict__ x)
{
    const int idx = blockIdx.x * 256 + threadIdx.x;   // float4 index
    const int row = idx >> 10;                        // DIN/4 = 1024 float4/row
    const int c4  = idx & 1023;
    const int col = c4 * 4;
    const float* src = (col < DHALF) ? &sbj[(size_t)row * DHALF + col]
                                     : &obj[(size_t)row * DHALF + col - DHALF];
    float4 v = *reinterpret_cast<const float4*>(src);
    v.x = fmaxf(v.x, 0.f); v.y = fmaxf(v.y, 0.f);
    v.z = fmaxf(v.z, 0.f); v.w = fmaxf(v.w, 0.f);
    *reinterpret_cast<float4*>(&x[(size_t)row * DIN + col]) = v;
}

// ---------------------------------------------------------------------------
// tf32 tensor GEMM: C = act(A @ W + bias), A [Mx K] row-major, W [K x 1024].
// BM=BN=64, BK=32, 256 thr = 8 warps (4m x 2n), warp tile 16x32.
// 3-stage cp.async ring, ONE __syncthreads per stage:
//   iter t: wait_group 1 -> sync -> issue(t+2) into buf (t+2)%3 -> mma(t)
// Commit exactly one group per iteration (empty on tail) so wait_group 1 is
// uniformly "stage t has landed".
// Bank-clean: As[m][k] stride 36 (4*l4+lq perm), Bs[k][n] stride 72 (8*lq+l4).
// Raw fp32 bits to HMMA.tf32 (HW truncates mantissa).
// ---------------------------------------------------------------------------
#define BM 64
#define BN 64
#define BK 32
#define AS_STR 36
#define BS_STR 72
#define AS_SZ  (BM * AS_STR)                 // 2304 floats
#define BS_SZ  (BK * BS_STR)                 // 2304 floats
#define STG_FL (AS_SZ + BS_SZ)               // 4608 floats
#define STG_BY (STG_FL * 4)                  // 18432 bytes
#define NSTAGE 3
#define SMEM_BYTES (NSTAGE * STG_BY)         // 55296

template <int RELU>
__global__ __launch_bounds__(256, 2)
void gemm_tc(const float* __restrict__ A, const float* __restrict__ Wmat,
             const float* __restrict__ bias, float* __restrict__ Cout, int K)
{
    extern __shared__ float sm[];
    const int T = K / BK;

    const int tid  = threadIdx.x;
    const int wid  = tid >> 5;
    const int lane = tid & 31;
    const int lq   = lane & 3;
    const int l4   = lane >> 2;

    const int m0 = blockIdx.y * BM;
    const int n0 = blockIdx.x * BN;
    const int wm = (wid & 3) * 16;
    const int wn = (wid >> 2) * 32;

    // load indexing: A tile 64r x 8 f4 (2/thread), B tile 32r x 16 f4 (2/thread)
    const int ar0 = tid >> 3, ac = tid & 7;     // rows 0..31, +32
    const int br0 = tid >> 4, bc = tid & 15;    // rows 0..15, +16

    // smem cp.async destinations (stage 0; add s*STG_BY per stage)
    const uint32_t smBase = smem_u32(sm);
    const uint32_t aD0 = smBase + (uint32_t)(ar0 * AS_STR + ac * 4) * 4;
    const uint32_t aD1 = smBase + (uint32_t)((ar0 + 32) * AS_STR + ac * 4) * 4;
    const uint32_t bD0 = smBase + (uint32_t)(AS_SZ + br0 * BS_STR + bc * 4) * 4;
    const uint32_t bD1 = smBase + (uint32_t)(AS_SZ + (br0 + 16) * BS_STR + bc * 4) * 4;

    // gmem running pointers (advance one stage per issue)
    const float* aS0 = &A[(size_t)(m0 + ar0) * K + ac * 4];
    const float* aS1 = &A[(size_t)(m0 + ar0 + 32) * K + ac * 4];
    const float* bS0 = &Wmat[(size_t)br0 * DOUT + n0 + bc * 4];
    const float* bS1 = &Wmat[(size_t)(br0 + 16) * DOUT + n0 + bc * 4];

    auto issue = [&](int s) {
        const uint32_t off = (uint32_t)s * STG_BY;
        CP16(aD0 + off, aS0);
        CP16(aD1 + off, aS1);
        CP16(bD0 + off, bS0);
        CP16(bD1 + off, bS1);
        aS0 += BK; aS1 += BK;
        bS0 += (size_t)BK * DOUT; bS1 += (size_t)BK * DOUT;
    };

    float acc[4][4];
    #pragma unroll
    for (int nj = 0; nj < 4; nj++)
        #pragma unroll
        for (int r = 0; r < 4; r++) acc[nj][r] = 0.f;

    // prologue: stages 0,1 -> buffers 0,1 (one commit group each)
    issue(0); CP_COMMIT();
    issue(1); CP_COMMIT();

    int buf = 0;        // buffer of stage t
    int sNext = 2;      // buffer for stage t+2

    for (int t = 0; t < T; t++) {
        asm volatile("cp.async.wait_group 1;" ::: "memory");
        __syncthreads();

        if (t + 2 < T) issue(sNext);
        CP_COMMIT();    // exactly one group per iteration (possibly empty)

        const float* Ab = sm + buf * STG_FL;
        const float* Bb = Ab + AS_SZ;

        #pragma unroll
        for (int k8 = 0; k8 < BK; k8 += 8) {
            const int R = wm + l4;
            uint32_t a0 = __float_as_uint(Ab[R * AS_STR + k8 + lq]);
            uint32_t a1 = __float_as_uint(Ab[(R + 8) * AS_STR + k8 + lq]);
            uint32_t a2 = __float_as_uint(Ab[R * AS_STR + k8 + lq + 4]);
            uint32_t a3 = __float_as_uint(Ab[(R + 8) * AS_STR + k8 + lq + 4]);
            uint32_t b[4][2];
            #pragma unroll
            for (int nj = 0; nj < 4; nj++) {
                const int Cn = wn + nj * 8 + l4;
                b[nj][0] = __float_as_uint(Bb[(k8 + lq) * BS_STR + Cn]);
                b[nj][1] = __float_as_uint(Bb[(k8 + lq + 4) * BS_STR + Cn]);
            }
            #pragma unroll
            for (int nj = 0; nj < 4; nj++)
                mma_tf32(acc[nj][0], acc[nj][1], acc[nj][2], acc[nj][3],
                         a0, a1, a2, a3, b[nj][0], b[nj][1]);
        }

        buf   = (buf == NSTAGE - 1) ? 0 : buf + 1;
        sNext = (sNext == NSTAGE - 1) ? 0 : sNext + 1;
    }

    // epilogue: bias (+relu)
    #pragma unroll
    for (int nj = 0; nj < 4; nj++) {
        const int col = n0 + wn + nj * 8 + lq * 2;
        const float bb0 = bias[col];
        const float bb1 = bias[col + 1];
        const int row = m0 + wm + l4;
        float o0 = acc[nj][0] + bb0;
        float o1 = acc[nj][1] + bb1;
        float o2 = acc[nj][2] + bb0;
        float o3 = acc[nj][3] + bb1;
        if (RELU) {
            o0 = fmaxf(o0, 0.f); o1 = fmaxf(o1, 0.f);
            o2 = fmaxf(o2, 0.f); o3 = fmaxf(o3, 0.f);
        }
        float2 p0 = {o0, o1};
        float2 p1 = {o2, o3};
        *reinterpret_cast<float2*>(&Cout[(size_t)row * DOUT + col])       = p0;
        *reinterpret_cast<float2*>(&Cout[(size_t)(row + 8) * DOUT + col]) = p1;
    }
}

// ---------------------------------------------------------------------------
// Scores: out[b,l] = -sqrt( sum_d relu(label[l,d] - emb[b,d])^2 )
// ---------------------------------------------------------------------------
__global__ __launch_bounds__(256)
void scores_kernel(const float* __restrict__ labels, float* __restrict__ out)
{
    __shared__ float Ls[NLAB][65];
    __shared__ float Es[8][65];

    const int tid = threadIdx.x;
    const int b0  = blockIdx.x * 8;
    const int l   = tid & 127;
    const int bg  = tid >> 7;

    float acc0 = 0.f, acc1 = 0.f, acc2 = 0.f, acc3 = 0.f;

    for (int k0 = 0; k0 < DOUT; k0 += 64) {
        #pragma unroll
        for (int j = 0; j < 8; j++) {
            int idx = tid + j * 256;
            int row = idx >> 4;
            int c4  = idx & 15;
            float4 v = *reinterpret_cast<const float4*>(
                &labels[(size_t)row * DOUT + k0 + c4 * 4]);
            Ls[row][c4 * 4 + 0] = v.x;
            Ls[row][c4 * 4 + 1] = v.y;
            Ls[row][c4 * 4 + 2] = v.z;
            Ls[row][c4 * 4 + 3] = v.w;
        }
        if (tid < 128) {
            int row = tid >> 4, c4 = tid & 15;
            float4 v = *reinterpret_cast<const float4*>(
                &g_emb[(size_t)(b0 + row) * DOUT + k0 + c4 * 4]);
            Es[row][c4 * 4 + 0] = v.x;
            Es[row][c4 * 4 + 1] = v.y;
            Es[row][c4 * 4 + 2] = v.z;
            Es[row][c4 * 4 + 3] = v.w;
        }
        __syncthreads();

        #pragma unroll 4
        for (int k = 0; k < 64; k++) {
            const float lk = Ls[l][k];
            float d0 = fmaxf(lk - Es[bg * 4 + 0][k], 0.f);
            float d1 = fmaxf(lk - Es[bg * 4 + 1][k], 0.f);
            float d2 = fmaxf(lk - Es[bg * 4 + 2][k], 0.f);
            float d3 = fmaxf(lk - Es[bg * 4 + 3][k], 0.f);
            acc0 = fmaf(d0, d0, acc0);
            acc1 = fmaf(d1, d1, acc1);
            acc2 = fmaf(d2, d2, acc2);
            acc3 = fmaf(d3, d3, acc3);
        }
        __syncthreads();
    }

    out[(size_t)(b0 + bg * 4 + 0) * NLAB + l] = -sqrtf(acc0);
    out[(size_t)(b0 + bg * 4 + 1) * NLAB + l] = -sqrtf(acc1);
    out[(size_t)(b0 + bg * 4 + 2) * NLAB + l] = -sqrtf(acc2);
    out[(size_t)(b0 + bg * 4 + 3) * NLAB + l] = -sqrtf(acc3);
}

// ---------------------------------------------------------------------------
// Launch
// ---------------------------------------------------------------------------
extern "C" void kernel_launch(void* const* d_in, const int* in_sizes, int n_in,
                              void* d_out, int out_size)
{
    const float* sbj    = (const float*)d_in[0];
    const float* obj    = (const float*)d_in[1];
    const float* W1     = (const float*)d_in[2];
    const float* b1     = (const float*)d_in[3];
    const float* W2     = (const float*)d_in[4];
    const float* b2     = (const float*)d_in[5];
    const float* labels = (const float*)d_in[6];
    float* out = (float*)d_out;

    float *x_ptr, *hidden_ptr, *emb_ptr;
    cudaGetSymbolAddress((void**)&x_ptr, g_x);
    cudaGetSymbolAddress((void**)&hidden_ptr, g_hidden);
    cudaGetSymbolAddress((void**)&emb_ptr, g_emb);

    cudaFuncSetAttribute(gemm_tc<1>, cudaFuncAttributeMaxDynamicSharedMemorySize, SMEM_BYTES);
    cudaFuncSetAttribute(gemm_tc<0>, cudaFuncAttributeMaxDynamicSharedMemorySize, SMEM_BYTES);

    relu_cat_kernel<<<(B_SZ * DIN / 4) / 256, 256>>>(sbj, obj, x_ptr);

    dim3 grid(DOUT / BN, B_SZ / BM);   // (16,16) = 256 CTAs
    gemm_tc<1><<<grid, 256, SMEM_BYTES>>>(x_ptr, W1, b1, hidden_ptr, DIN);
    gemm_tc<0><<<grid, 256, SMEM_BYTES>>>(hidden_ptr, W2, b2, emb_ptr, DOUT);

    scores_kernel<<<B_SZ / 8, 256>>>(labels, out);
}

// round 6
// speedup vs baseline: 2.3789x; 1.0945x over previous
#include <cuda_runtime.h>
#include <cstdint>

#define B_SZ  1024
#define DHALF 2048
#define DIN   4096
#define DOUT  1024
#define NLAB  128

// Scratch (allocation-free rule: __device__ globals)
__device__ float g_x[B_SZ * DIN];        // relu(concat(sbj,obj))
__device__ float g_hidden[B_SZ * DOUT];  // relu(hidden)
__device__ float g_emb[B_SZ * DOUT];     // emb

// ---------------------------------------------------------------------------
// helpers
// ---------------------------------------------------------------------------
__device__ __forceinline__ uint32_t smem_u32(const void* p) {
    uint32_t a;
    asm("{ .reg .u64 t; cvta.to.shared.u64 t, %1; cvt.u32.u64 %0, t; }"
        : "=r"(a) : "l"(p));
    return a;
}
#define CP16(dst, src) asm volatile("cp.async.cg.shared.global [%0], [%1], 16;" :: "r"(dst), "l"(src) : "memory")
#define CP_COMMIT()    asm volatile("cp.async.commit_group;" ::: "memory")

__device__ __forceinline__ void mma_tf32(float& c0, float& c1, float& c2, float& c3,
                                         uint32_t a0, uint32_t a1, uint32_t a2, uint32_t a3,
                                         uint32_t b0, uint32_t b1) {
    asm volatile(
        "mma.sync.aligned.m16n8k8.row.col.f32.tf32.tf32.f32 "
        "{%0,%1,%2,%3}, {%4,%5,%6,%7}, {%8,%9}, {%0,%1,%2,%3};"
        : "+f"(c0), "+f"(c1), "+f"(c2), "+f"(c3)
        : "r"(a0), "r"(a1), "r"(a2), "r"(a3), "r"(b0), "r"(b1));
}

// ---------------------------------------------------------------------------
// Prepass: g_x[m][k] = relu(concat(sbj,obj))
// ---------------------------------------------------------------------------
__global__ __launch_bounds__(256)
void relu_cat_kernel(const float* __restrict__ sbj, const float* __restrict__ obj,
                     float* __restrict__ x)
{
    const int idx = blockIdx.x * 256 + threadIdx.x;
    const int row = idx >> 10;
    const int c4  = idx & 1023;
    const int col = c4 * 4;
    const float* src = (col < DHALF) ? &sbj[(size_t)row * DHALF + col]
                                     : &obj[(size_t)row * DHALF + col - DHALF];
    float4 v = *reinterpret_cast<const float4*>(src);
    v.x = fmaxf(v.x, 0.f); v.y = fmaxf(v.y, 0.f);
    v.z = fmaxf(v.z, 0.f); v.w = fmaxf(v.w, 0.f);
    *reinterpret_cast<float4*>(&x[(size_t)row * DIN + col]) = v;
}

// ---------------------------------------------------------------------------
// tf32 tensor GEMM: C = act(A @ W + bias)
// BM=BN=64, BK=32, 8 warps (4m x 2n), warp tile 16x32.
// 4-stage cp.async ring, ONE __syncthreads per stage:
//   iter t: wait_group 2 -> sync -> issue(t+3) -> commit -> mma(t)
// Bank-clean: As stride 36, Bs stride 72.
// ---------------------------------------------------------------------------
#define BM 64
#define BN 64
#define BK 32
#define AS_STR 36
#define BS_STR 72
#define AS_SZ  (BM * AS_STR)
#define BS_SZ  (BK * BS_STR)
#define STG_FL (AS_SZ + BS_SZ)      // 4608 floats
#define STG_BY (STG_FL * 4)         // 18432 bytes
#define NSTAGE 4
#define GEMM_SMEM (NSTAGE * STG_BY) // 73728

template <int RELU>
__global__ __launch_bounds__(256, 2)
void gemm_tc(const float* __restrict__ A, const float* __restrict__ Wmat,
             const float* __restrict__ bias, float* __restrict__ Cout, int K)
{
    extern __shared__ float sm[];
    const int T = K / BK;

    const int tid  = threadIdx.x;
    const int wid  = tid >> 5;
    const int lane = tid & 31;
    const int lq   = lane & 3;
    const int l4   = lane >> 2;

    const int m0 = blockIdx.y * BM;
    const int n0 = blockIdx.x * BN;
    const int wm = (wid & 3) * 16;
    const int wn = (wid >> 2) * 32;

    const int ar0 = tid >> 3, ac = tid & 7;
    const int br0 = tid >> 4, bc = tid & 15;

    const uint32_t smBase = smem_u32(sm);
    const uint32_t aD0 = smBase + (uint32_t)(ar0 * AS_STR + ac * 4) * 4;
    const uint32_t aD1 = smBase + (uint32_t)((ar0 + 32) * AS_STR + ac * 4) * 4;
    const uint32_t bD0 = smBase + (uint32_t)(AS_SZ + br0 * BS_STR + bc * 4) * 4;
    const uint32_t bD1 = smBase + (uint32_t)(AS_SZ + (br0 + 16) * BS_STR + bc * 4) * 4;

    const float* aS0 = &A[(size_t)(m0 + ar0) * K + ac * 4];
    const float* aS1 = &A[(size_t)(m0 + ar0 + 32) * K + ac * 4];
    const float* bS0 = &Wmat[(size_t)br0 * DOUT + n0 + bc * 4];
    const float* bS1 = &Wmat[(size_t)(br0 + 16) * DOUT + n0 + bc * 4];

    auto issue = [&](int s) {
        const uint32_t off = (uint32_t)s * STG_BY;
        CP16(aD0 + off, aS0);
        CP16(aD1 + off, aS1);
        CP16(bD0 + off, bS0);
        CP16(bD1 + off, bS1);
        aS0 += BK; aS1 += BK;
        bS0 += (size_t)BK * DOUT; bS1 += (size_t)BK * DOUT;
    };

    float acc[4][4];
    #pragma unroll
    for (int nj = 0; nj < 4; nj++)
        #pragma unroll
        for (int r = 0; r < 4; r++) acc[nj][r] = 0.f;

    // prologue: stages 0..2
    issue(0); CP_COMMIT();
    issue(1); CP_COMMIT();
    issue(2); CP_COMMIT();

    int buf = 0;        // buffer of stage t
    int sNext = 3;      // buffer for stage t+3

    for (int t = 0; t < T; t++) {
        asm volatile("cp.async.wait_group 2;" ::: "memory");
        __syncthreads();

        if (t + 3 < T) issue(sNext);
        CP_COMMIT();    // exactly one group per iteration

        const float* Ab = sm + buf * STG_FL;
        const float* Bb = Ab + AS_SZ;

        #pragma unroll
        for (int k8 = 0; k8 < BK; k8 += 8) {
            const int R = wm + l4;
            uint32_t a0 = __float_as_uint(Ab[R * AS_STR + k8 + lq]);
            uint32_t a1 = __float_as_uint(Ab[(R + 8) * AS_STR + k8 + lq]);
            uint32_t a2 = __float_as_uint(Ab[R * AS_STR + k8 + lq + 4]);
            uint32_t a3 = __float_as_uint(Ab[(R + 8) * AS_STR + k8 + lq + 4]);
            uint32_t b[4][2];
            #pragma unroll
            for (int nj = 0; nj < 4; nj++) {
                const int Cn = wn + nj * 8 + l4;
                b[nj][0] = __float_as_uint(Bb[(k8 + lq) * BS_STR + Cn]);
                b[nj][1] = __float_as_uint(Bb[(k8 + lq + 4) * BS_STR + Cn]);
            }
            #pragma unroll
            for (int nj = 0; nj < 4; nj++)
                mma_tf32(acc[nj][0], acc[nj][1], acc[nj][2], acc[nj][3],
                         a0, a1, a2, a3, b[nj][0], b[nj][1]);
        }

        buf   = (buf == NSTAGE - 1) ? 0 : buf + 1;
        sNext = (sNext == NSTAGE - 1) ? 0 : sNext + 1;
    }

    #pragma unroll
    for (int nj = 0; nj < 4; nj++) {
        const int col = n0 + wn + nj * 8 + lq * 2;
        const float bb0 = bias[col];
        const float bb1 = bias[col + 1];
        const int row = m0 + wm + l4;
        float o0 = acc[nj][0] + bb0;
        float o1 = acc[nj][1] + bb1;
        float o2 = acc[nj][2] + bb0;
        float o3 = acc[nj][3] + bb1;
        if (RELU) {
            o0 = fmaxf(o0, 0.f); o1 = fmaxf(o1, 0.f);
            o2 = fmaxf(o2, 0.f); o3 = fmaxf(o3, 0.f);
        }
        float2 p0 = {o0, o1};
        float2 p1 = {o2, o3};
        *reinterpret_cast<float2*>(&Cout[(size_t)row * DOUT + col])       = p0;
        *reinterpret_cast<float2*>(&Cout[(size_t)(row + 8) * DOUT + col]) = p1;
    }
}

// ---------------------------------------------------------------------------
// Scores v2: out[b,l] = -sqrt( sum_d relu(label[l,d] - emb[b,d])^2 )
// grid 128 (8 b-rows/CTA), 256 threads: l = tid&127, bg = tid>>7 -> 4 rows.
// k chunked by 64; cp.async double-buffered stages (labels + emb), float4
// compute. Ls stride 68 floats (17 x float4): LDS.128 at l*17+k4 chunk index,
// 17*l mod 8 distinct per 8-lane phase -> conflict-free.
// Stage layout (floats): [Ls 128*68 | Es 8*68] = 9248; two stages = 73984 B.
// ---------------------------------------------------------------------------
#define LS_STR 68
#define SC_STG (NLAB * LS_STR + 8 * LS_STR)     // 9248 floats
#define SC_SMEM (2 * SC_STG * 4)                // 73984 bytes
#define NCHUNK (DOUT / 64)                      // 16

__global__ __launch_bounds__(256)
void scores_kernel(const float* __restrict__ labels, const float* __restrict__ emb,
                   float* __restrict__ out)
{
    extern __shared__ float sm[];
    const int tid = threadIdx.x;
    const int b0  = blockIdx.x * 8;
    const int l   = tid & 127;
    const int bg  = tid >> 7;

    const uint32_t smBase = smem_u32(sm);

    // fill indexing: Ls 128 rows x 16 float4 (8/thread); Es 8 x 16 f4 (tid<128)
    const int lr = tid >> 4, lc = tid & 15;     // also rows lr+16*j
    auto issue = [&](int c, int buf) {
        const int k0 = c * 64;
        const uint32_t off = (uint32_t)buf * (SC_STG * 4);
        #pragma unroll
        for (int j = 0; j < 8; j++) {
            const int row = lr + j * 16;
            CP16(smBase + off + (uint32_t)(row * LS_STR + lc * 4) * 4,
                 &labels[(size_t)row * DOUT + k0 + lc * 4]);
        }
        if (tid < 128) {
            const int row = tid >> 4, c4 = tid & 15;
            CP16(smBase + off + (uint32_t)(NLAB * LS_STR + row * LS_STR + c4 * 4) * 4,
                 &emb[(size_t)(b0 + row) * DOUT + k0 + c4 * 4]);
        }
    };

    float acc0 = 0.f, acc1 = 0.f, acc2 = 0.f, acc3 = 0.f;

    issue(0, 0); CP_COMMIT();

    for (int c = 0; c < NCHUNK; c++) {
        const int buf = c & 1;
        if (c + 1 < NCHUNK) { issue(c + 1, buf ^ 1); }
        CP_COMMIT();   // one group per iteration (possibly empty)
        asm volatile("cp.async.wait_group 1;" ::: "memory");
        __syncthreads();

        const float* Sb = sm + buf * SC_STG;
        const float4* Lp = reinterpret_cast<const float4*>(Sb + l * LS_STR);
        const float* Ep = Sb + NLAB * LS_STR + (bg * 4) * LS_STR;

        #pragma unroll
        for (int k4 = 0; k4 < 16; k4++) {
            const float4 lv = Lp[k4];
            const float4 e0 = *reinterpret_cast<const float4*>(Ep + 0 * LS_STR + k4 * 4);
            const float4 e1 = *reinterpret_cast<const float4*>(Ep + 1 * LS_STR + k4 * 4);
            const float4 e2 = *reinterpret_cast<const float4*>(Ep + 2 * LS_STR + k4 * 4);
            const float4 e3 = *reinterpret_cast<const float4*>(Ep + 3 * LS_STR + k4 * 4);
            float d;
            d = fmaxf(lv.x - e0.x, 0.f); acc0 = fmaf(d, d, acc0);
            d = fmaxf(lv.y - e0.y, 0.f); acc0 = fmaf(d, d, acc0);
            d = fmaxf(lv.z - e0.z, 0.f); acc0 = fmaf(d, d, acc0);
            d = fmaxf(lv.w - e0.w, 0.f); acc0 = fmaf(d, d, acc0);
            d = fmaxf(lv.x - e1.x, 0.f); acc1 = fmaf(d, d, acc1);
            d = fmaxf(lv.y - e1.y, 0.f); acc1 = fmaf(d, d, acc1);
            d = fmaxf(lv.z - e1.z, 0.f); acc1 = fmaf(d, d, acc1);
            d = fmaxf(lv.w - e1.w, 0.f); acc1 = fmaf(d, d, acc1);
            d = fmaxf(lv.x - e2.x, 0.f); acc2 = fmaf(d, d, acc2);
            d = fmaxf(lv.y - e2.y, 0.f); acc2 = fmaf(d, d, acc2);
            d = fmaxf(lv.z - e2.z, 0.f); acc2 = fmaf(d, d, acc2);
            d = fmaxf(lv.w - e2.w, 0.f); acc2 = fmaf(d, d, acc2);
            d = fmaxf(lv.x - e3.x, 0.f); acc3 = fmaf(d, d, acc3);
            d = fmaxf(lv.y - e3.y, 0.f); acc3 = fmaf(d, d, acc3);
            d = fmaxf(lv.z - e3.z, 0.f); acc3 = fmaf(d, d, acc3);
            d = fmaxf(lv.w - e3.w, 0.f); acc3 = fmaf(d, d, acc3);
        }
        __syncthreads();   // all reads of buf done before issue overwrites it
    }

    out[(size_t)(b0 + bg * 4 + 0) * NLAB + l] = -sqrtf(acc0);
    out[(size_t)(b0 + bg * 4 + 1) * NLAB + l] = -sqrtf(acc1);
    out[(size_t)(b0 + bg * 4 + 2) * NLAB + l] = -sqrtf(acc2);
    out[(size_t)(b0 + bg * 4 + 3) * NLAB + l] = -sqrtf(acc3);
}

// ---------------------------------------------------------------------------
// Launch
// ---------------------------------------------------------------------------
extern "C" void kernel_launch(void* const* d_in, const int* in_sizes, int n_in,
                              void* d_out, int out_size)
{
    const float* sbj    = (const float*)d_in[0];
    const float* obj    = (const float*)d_in[1];
    const float* W1     = (const float*)d_in[2];
    const float* b1     = (const float*)d_in[3];
    const float* W2     = (const float*)d_in[4];
    const float* b2     = (const float*)d_in[5];
    const float* labels = (const float*)d_in[6];
    float* out = (float*)d_out;

    float *x_ptr, *hidden_ptr, *emb_ptr;
    cudaGetSymbolAddress((void**)&x_ptr, g_x);
    cudaGetSymbolAddress((void**)&hidden_ptr, g_hidden);
    cudaGetSymbolAddress((void**)&emb_ptr, g_emb);

    cudaFuncSetAttribute(gemm_tc<1>, cudaFuncAttributeMaxDynamicSharedMemorySize, GEMM_SMEM);
    cudaFuncSetAttribute(gemm_tc<0>, cudaFuncAttributeMaxDynamicSharedMemorySize, GEMM_SMEM);
    cudaFuncSetAttribute(scores_kernel, cudaFuncAttributeMaxDynamicSharedMemorySize, SC_SMEM);

    relu_cat_kernel<<<(B_SZ * DIN / 4) / 256, 256>>>(sbj, obj, x_ptr);

    dim3 grid(DOUT / BN, B_SZ / BM);   // (16,16) = 256 CTAs
    gemm_tc<1><<<grid, 256, GEMM_SMEM>>>(x_ptr, W1, b1, hidden_ptr, DIN);
    gemm_tc<0><<<grid, 256, GEMM_SMEM>>>(hidden_ptr, W2, b2, emb_ptr, DOUT);

    scores_kernel<<<B_SZ / 8, 256, SC_SMEM>>>(labels, emb_ptr, out);
}

// round 7
// speedup vs baseline: 2.4074x; 1.0120x over previous
#include <cuda_runtime.h>
#include <cstdint>

#define B_SZ  1024
#define DHALF 2048
#define DIN   4096
#define DOUT  1024
#define NLAB  128

// Scratch (allocation-free rule: __device__ globals)
__device__ float g_x[B_SZ * DIN];          // relu(concat(sbj,obj))
__device__ float g_hidden[B_SZ * DOUT];    // relu(hidden)
__device__ float g_emb[B_SZ * DOUT];       // emb
__device__ float g_part[2 * B_SZ * NLAB];  // scores split-k partials

// ---------------------------------------------------------------------------
// helpers
// ---------------------------------------------------------------------------
__device__ __forceinline__ uint32_t smem_u32(const void* p) {
    uint32_t a;
    asm("{ .reg .u64 t; cvta.to.shared.u64 t, %1; cvt.u32.u64 %0, t; }"
        : "=r"(a) : "l"(p));
    return a;
}
#define CP16(dst, src) asm volatile("cp.async.cg.shared.global [%0], [%1], 16;" :: "r"(dst), "l"(src) : "memory")
#define CP_COMMIT()    asm volatile("cp.async.commit_group;" ::: "memory")

__device__ __forceinline__ void mma_tf32(float& c0, float& c1, float& c2, float& c3,
                                         uint32_t a0, uint32_t a1, uint32_t a2, uint32_t a3,
                                         uint32_t b0, uint32_t b1) {
    asm volatile(
        "mma.sync.aligned.m16n8k8.row.col.f32.tf32.tf32.f32 "
        "{%0,%1,%2,%3}, {%4,%5,%6,%7}, {%8,%9}, {%0,%1,%2,%3};"
        : "+f"(c0), "+f"(c1), "+f"(c2), "+f"(c3)
        : "r"(a0), "r"(a1), "r"(a2), "r"(a3), "r"(b0), "r"(b1));
}

// ---------------------------------------------------------------------------
// Prepass: g_x[m][k] = relu(concat(sbj,obj))
// ---------------------------------------------------------------------------
__global__ __launch_bounds__(256)
void relu_cat_kernel(const float* __restrict__ sbj, const float* __restrict__ obj,
                     float* __restrict__ x)
{
    const int idx = blockIdx.x * 256 + threadIdx.x;
    const int row = idx >> 10;
    const int c4  = idx & 1023;
    const int col = c4 * 4;
    const float* src = (col < DHALF) ? &sbj[(size_t)row * DHALF + col]
                                     : &obj[(size_t)row * DHALF + col - DHALF];
    float4 v = *reinterpret_cast<const float4*>(src);
    v.x = fmaxf(v.x, 0.f); v.y = fmaxf(v.y, 0.f);
    v.z = fmaxf(v.z, 0.f); v.w = fmaxf(v.w, 0.f);
    *reinterpret_cast<float4*>(&x[(size_t)row * DIN + col]) = v;
}

// ---------------------------------------------------------------------------
// tf32 tensor GEMM: C = act(A @ W + bias)
// BM=BN=64, BK=64 (fat stages: half the barriers/latency exposures of BK=32).
// 8 warps (4m x 2n), warp tile 16x32. 3-stage cp.async ring, ONE sync/stage:
//   iter t: wait_group 1 -> sync -> issue(t+2) -> commit -> mma(t)
// Bank-clean: As[m][k] stride 68 (68*l4+lq mod 32 covers all banks),
//             Bs[k][n] stride 72 (8*lq+l4 perm).
// ---------------------------------------------------------------------------
#define BM 64
#define BN 64
#define BK 64
#define AS_STR 68
#define BS_STR 72
#define AS_SZ  (BM * AS_STR)        // 4352 floats
#define BS_SZ  (BK * BS_STR)        // 4608 floats
#define STG_FL (AS_SZ + BS_SZ)      // 8960 floats
#define STG_BY (STG_FL * 4)         // 35840 bytes
#define NSTAGE 3
#define GEMM_SMEM (NSTAGE * STG_BY) // 107520

template <int RELU>
__global__ __launch_bounds__(256, 2)
void gemm_tc(const float* __restrict__ A, const float* __restrict__ Wmat,
             const float* __restrict__ bias, float* __restrict__ Cout, int K)
{
    extern __shared__ float sm[];
    const int T = K / BK;

    const int tid  = threadIdx.x;
    const int wid  = tid >> 5;
    const int lane = tid & 31;
    const int lq   = lane & 3;
    const int l4   = lane >> 2;

    const int m0 = blockIdx.y * BM;
    const int n0 = blockIdx.x * BN;
    const int wm = (wid & 3) * 16;
    const int wn = (wid >> 2) * 32;

    // fills: A tile 64r x 16 f4 (4/thread), B tile 64r x 16 f4 (4/thread)
    const int fr = tid >> 4, fc = tid & 15;   // rows fr+16j, col fc*4

    const uint32_t smBase = smem_u32(sm);
    uint32_t aD[4], bD[4];
    #pragma unroll
    for (int j = 0; j < 4; j++) {
        aD[j] = smBase + (uint32_t)((fr + 16 * j) * AS_STR + fc * 4) * 4;
        bD[j] = smBase + (uint32_t)(AS_SZ + (fr + 16 * j) * BS_STR + fc * 4) * 4;
    }

    const float* aS = &A[(size_t)(m0 + fr) * K + fc * 4];          // +16j rows
    const float* bS = &Wmat[(size_t)fr * DOUT + n0 + fc * 4];      // +16j rows

    auto issue = [&](int s) {
        const uint32_t off = (uint32_t)s * STG_BY;
        #pragma unroll
        for (int j = 0; j < 4; j++)
            CP16(aD[j] + off, aS + (size_t)(16 * j) * K);
        #pragma unroll
        for (int j = 0; j < 4; j++)
            CP16(bD[j] + off, bS + (size_t)(16 * j) * DOUT);
        aS += BK;
        bS += (size_t)BK * DOUT;
    };

    float acc[4][4];
    #pragma unroll
    for (int nj = 0; nj < 4; nj++)
        #pragma unroll
        for (int r = 0; r < 4; r++) acc[nj][r] = 0.f;

    issue(0); CP_COMMIT();
    issue(1); CP_COMMIT();

    int buf = 0, sNext = 2;

    for (int t = 0; t < T; t++) {
        asm volatile("cp.async.wait_group 1;" ::: "memory");
        __syncthreads();

        if (t + 2 < T) issue(sNext);
        CP_COMMIT();    // exactly one group per iteration

        const float* Ab = sm + buf * STG_FL;
        const float* Bb = Ab + AS_SZ;

        #pragma unroll
        for (int k8 = 0; k8 < BK; k8 += 8) {
            const int R = wm + l4;
            uint32_t a0 = __float_as_uint(Ab[R * AS_STR + k8 + lq]);
            uint32_t a1 = __float_as_uint(Ab[(R + 8) * AS_STR + k8 + lq]);
            uint32_t a2 = __float_as_uint(Ab[R * AS_STR + k8 + lq + 4]);
            uint32_t a3 = __float_as_uint(Ab[(R + 8) * AS_STR + k8 + lq + 4]);
            uint32_t b[4][2];
            #pragma unroll
            for (int nj = 0; nj < 4; nj++) {
                const int Cn = wn + nj * 8 + l4;
                b[nj][0] = __float_as_uint(Bb[(k8 + lq) * BS_STR + Cn]);
                b[nj][1] = __float_as_uint(Bb[(k8 + lq + 4) * BS_STR + Cn]);
            }
            #pragma unroll
            for (int nj = 0; nj < 4; nj++)
                mma_tf32(acc[nj][0], acc[nj][1], acc[nj][2], acc[nj][3],
                         a0, a1, a2, a3, b[nj][0], b[nj][1]);
        }

        buf   = (buf == NSTAGE - 1) ? 0 : buf + 1;
        sNext = (sNext == NSTAGE - 1) ? 0 : sNext + 1;
    }

    #pragma unroll
    for (int nj = 0; nj < 4; nj++) {
        const int col = n0 + wn + nj * 8 + lq * 2;
        const float bb0 = bias[col];
        const float bb1 = bias[col + 1];
        const int row = m0 + wm + l4;
        float o0 = acc[nj][0] + bb0;
        float o1 = acc[nj][1] + bb1;
        float o2 = acc[nj][2] + bb0;
        float o3 = acc[nj][3] + bb1;
        if (RELU) {
            o0 = fmaxf(o0, 0.f); o1 = fmaxf(o1, 0.f);
            o2 = fmaxf(o2, 0.f); o3 = fmaxf(o3, 0.f);
        }
        float2 p0 = {o0, o1};
        float2 p1 = {o2, o3};
        *reinterpret_cast<float2*>(&Cout[(size_t)row * DOUT + col])       = p0;
        *reinterpret_cast<float2*>(&Cout[(size_t)(row + 8) * DOUT + col]) = p1;
    }
}

// ---------------------------------------------------------------------------
// Scores split-k: partial[h][b][l] = sum_{d in half h} relu(label-emb)^2
// grid (128, 2): x = 8-row b-group, y = k-half. 256 threads: l=tid&127,
// bg=tid>>7 -> 4 rows each. cp.async double-buffered 64-wide k chunks.
// ---------------------------------------------------------------------------
#define LS_STR 68
#define SC_STG (NLAB * LS_STR + 8 * LS_STR)     // 9248 floats
#define SC_SMEM (2 * SC_STG * 4)                // 73984 bytes
#define NCHUNK_H 8                              // 512 k per half / 64

__global__ __launch_bounds__(256)
void scores_part_kernel(const float* __restrict__ labels,
                        const float* __restrict__ emb,
                        float* __restrict__ part)
{
    extern __shared__ float sm[];
    const int tid = threadIdx.x;
    const int b0  = blockIdx.x * 8;
    const int kh  = blockIdx.y * (DOUT / 2);
    const int l   = tid & 127;
    const int bg  = tid >> 7;

    const uint32_t smBase = smem_u32(sm);
    const int lr = tid >> 4, lc = tid & 15;

    auto issue = [&](int c, int buf) {
        const int k0 = kh + c * 64;
        const uint32_t off = (uint32_t)buf * (SC_STG * 4);
        #pragma unroll
        for (int j = 0; j < 8; j++) {
            const int row = lr + j * 16;
            CP16(smBase + off + (uint32_t)(row * LS_STR + lc * 4) * 4,
                 &labels[(size_t)row * DOUT + k0 + lc * 4]);
        }
        if (tid < 128) {
            const int row = tid >> 4, c4 = tid & 15;
            CP16(smBase + off + (uint32_t)(NLAB * LS_STR + row * LS_STR + c4 * 4) * 4,
                 &emb[(size_t)(b0 + row) * DOUT + k0 + c4 * 4]);
        }
    };

    float acc0 = 0.f, acc1 = 0.f, acc2 = 0.f, acc3 = 0.f;

    issue(0, 0); CP_COMMIT();

    for (int c = 0; c < NCHUNK_H; c++) {
        const int buf = c & 1;
        if (c + 1 < NCHUNK_H) { issue(c + 1, buf ^ 1); }
        CP_COMMIT();
        asm volatile("cp.async.wait_group 1;" ::: "memory");
        __syncthreads();

        const float* Sb = sm + buf * SC_STG;
        const float4* Lp = reinterpret_cast<const float4*>(Sb + l * LS_STR);
        const float* Ep = Sb + NLAB * LS_STR + (bg * 4) * LS_STR;

        #pragma unroll
        for (int k4 = 0; k4 < 16; k4++) {
            const float4 lv = Lp[k4];
            const float4 e0 = *reinterpret_cast<const float4*>(Ep + 0 * LS_STR + k4 * 4);
            const float4 e1 = *reinterpret_cast<const float4*>(Ep + 1 * LS_STR + k4 * 4);
            const float4 e2 = *reinterpret_cast<const float4*>(Ep + 2 * LS_STR + k4 * 4);
            const float4 e3 = *reinterpret_cast<const float4*>(Ep + 3 * LS_STR + k4 * 4);
            float d;
            d = fmaxf(lv.x - e0.x, 0.f); acc0 = fmaf(d, d, acc0);
            d = fmaxf(lv.y - e0.y, 0.f); acc0 = fmaf(d, d, acc0);
            d = fmaxf(lv.z - e0.z, 0.f); acc0 = fmaf(d, d, acc0);
            d = fmaxf(lv.w - e0.w, 0.f); acc0 = fmaf(d, d, acc0);
            d = fmaxf(lv.x - e1.x, 0.f); acc1 = fmaf(d, d, acc1);
            d = fmaxf(lv.y - e1.y, 0.f); acc1 = fmaf(d, d, acc1);
            d = fmaxf(lv.z - e1.z, 0.f); acc1 = fmaf(d, d, acc1);
            d = fmaxf(lv.w - e1.w, 0.f); acc1 = fmaf(d, d, acc1);
            d = fmaxf(lv.x - e2.x, 0.f); acc2 = fmaf(d, d, acc2);
            d = fmaxf(lv.y - e2.y, 0.f); acc2 = fmaf(d, d, acc2);
            d = fmaxf(lv.z - e2.z, 0.f); acc2 = fmaf(d, d, acc2);
            d = fmaxf(lv.w - e2.w, 0.f); acc2 = fmaf(d, d, acc2);
            d = fmaxf(lv.x - e3.x, 0.f); acc3 = fmaf(d, d, acc3);
            d = fmaxf(lv.y - e3.y, 0.f); acc3 = fmaf(d, d, acc3);
            d = fmaxf(lv.z - e3.z, 0.f); acc3 = fmaf(d, d, acc3);
            d = fmaxf(lv.w - e3.w, 0.f); acc3 = fmaf(d, d, acc3);
        }
        __syncthreads();
    }

    float* dst = part + (size_t)blockIdx.y * (B_SZ * NLAB);
    dst[(size_t)(b0 + bg * 4 + 0) * NLAB + l] = acc0;
    dst[(size_t)(b0 + bg * 4 + 1) * NLAB + l] = acc1;
    dst[(size_t)(b0 + bg * 4 + 2) * NLAB + l] = acc2;
    dst[(size_t)(b0 + bg * 4 + 3) * NLAB + l] = acc3;
}

__global__ __launch_bounds__(256)
void scores_reduce_kernel(const float* __restrict__ part, float* __restrict__ out)
{
    const int idx = blockIdx.x * 256 + threadIdx.x;   // 0 .. 131071
    out[idx] = -sqrtf(part[idx] + part[B_SZ * NLAB + idx]);
}

// ---------------------------------------------------------------------------
// Launch
// ---------------------------------------------------------------------------
extern "C" void kernel_launch(void* const* d_in, const int* in_sizes, int n_in,
                              void* d_out, int out_size)
{
    const float* sbj    = (const float*)d_in[0];
    const float* obj    = (const float*)d_in[1];
    const float* W1     = (const float*)d_in[2];
    const float* b1     = (const float*)d_in[3];
    const float* W2     = (const float*)d_in[4];
    const float* b2     = (const float*)d_in[5];
    const float* labels = (const float*)d_in[6];
    float* out = (float*)d_out;

    float *x_ptr, *hidden_ptr, *emb_ptr, *part_ptr;
    cudaGetSymbolAddress((void**)&x_ptr, g_x);
    cudaGetSymbolAddress((void**)&hidden_ptr, g_hidden);
    cudaGetSymbolAddress((void**)&emb_ptr, g_emb);
    cudaGetSymbolAddress((void**)&part_ptr, g_part);

    cudaFuncSetAttribute(gemm_tc<1>, cudaFuncAttributeMaxDynamicSharedMemorySize, GEMM_SMEM);
    cudaFuncSetAttribute(gemm_tc<0>, cudaFuncAttributeMaxDynamicSharedMemorySize, GEMM_SMEM);
    cudaFuncSetAttribute(scores_part_kernel, cudaFuncAttributeMaxDynamicSharedMemorySize, SC_SMEM);

    relu_cat_kernel<<<(B_SZ * DIN / 4) / 256, 256>>>(sbj, obj, x_ptr);

    dim3 grid(DOUT / BN, B_SZ / BM);   // (16,16) = 256 CTAs
    gemm_tc<1><<<grid, 256, GEMM_SMEM>>>(x_ptr, W1, b1, hidden_ptr, DIN);
    gemm_tc<0><<<grid, 256, GEMM_SMEM>>>(hidden_ptr, W2, b2, emb_ptr, DOUT);

    scores_part_kernel<<<dim3(B_SZ / 8, 2), 256, SC_SMEM>>>(labels, emb_ptr, part_ptr);
    scores_reduce_kernel<<<(B_SZ * NLAB) / 256, 256>>>(part_ptr, out);
}

// round 8
// speedup vs baseline: 2.4464x; 1.0162x over previous
#include <cuda_runtime.h>
#include <cstdint>

#define B_SZ  1024
#define DHALF 2048
#define DIN   4096
#define DOUT  1024
#define NLAB  128
#define KSPLIT 4

// Scratch (allocation-free rule: __device__ globals)
__device__ float g_x[B_SZ * DIN];               // relu(concat(sbj,obj))
__device__ float g_hidden[B_SZ * DOUT];         // relu(hidden)
__device__ float g_emb[B_SZ * DOUT];            // emb
__device__ float g_part[KSPLIT * B_SZ * NLAB];  // scores split-k partials

// ---------------------------------------------------------------------------
// helpers
// ---------------------------------------------------------------------------
__device__ __forceinline__ uint32_t smem_u32(const void* p) {
    uint32_t a;
    asm("{ .reg .u64 t; cvta.to.shared.u64 t, %1; cvt.u32.u64 %0, t; }"
        : "=r"(a) : "l"(p));
    return a;
}
#define CP16(dst, src) asm volatile("cp.async.cg.shared.global [%0], [%1], 16;" :: "r"(dst), "l"(src) : "memory")
#define CP_COMMIT()    asm volatile("cp.async.commit_group;" ::: "memory")

__device__ __forceinline__ void mma_tf32(float& c0, float& c1, float& c2, float& c3,
                                         uint32_t a0, uint32_t a1, uint32_t a2, uint32_t a3,
                                         uint32_t b0, uint32_t b1) {
    asm volatile(
        "mma.sync.aligned.m16n8k8.row.col.f32.tf32.tf32.f32 "
        "{%0,%1,%2,%3}, {%4,%5,%6,%7}, {%8,%9}, {%0,%1,%2,%3};"
        : "+f"(c0), "+f"(c1), "+f"(c2), "+f"(c3)
        : "r"(a0), "r"(a1), "r"(a2), "r"(a3), "r"(b0), "r"(b1));
}

// ---------------------------------------------------------------------------
// Prepass: g_x[m][k] = relu(concat(sbj,obj))
// ---------------------------------------------------------------------------
__global__ __launch_bounds__(256)
void relu_cat_kernel(const float* __restrict__ sbj, const float* __restrict__ obj,
                     float* __restrict__ x)
{
    const int idx = blockIdx.x * 256 + threadIdx.x;
    const int row = idx >> 10;
    const int c4  = idx & 1023;
    const int col = c4 * 4;
    const float* src = (col < DHALF) ? &sbj[(size_t)row * DHALF + col]
                                     : &obj[(size_t)row * DHALF + col - DHALF];
    float4 v = *reinterpret_cast<const float4*>(src);
    v.x = fmaxf(v.x, 0.f); v.y = fmaxf(v.y, 0.f);
    v.z = fmaxf(v.z, 0.f); v.w = fmaxf(v.w, 0.f);
    *reinterpret_cast<float4*>(&x[(size_t)row * DIN + col]) = v;
}

// ---------------------------------------------------------------------------
// tf32 tensor GEMM (R5 measured-best config): C = act(A @ W + bias)
// BM=BN=64, BK=32, 8 warps (4m x 2n), warp tile 16x32.
// 3-stage cp.async ring, ONE __syncthreads per stage:
//   iter t: wait_group 1 -> sync -> issue(t+2) -> commit -> mma(t)
// Bank-clean: As stride 36 (4*l4+lq perm), Bs stride 72 (8*lq+l4 perm).
// ---------------------------------------------------------------------------
#define BM 64
#define BN 64
#define BK 32
#define AS_STR 36
#define BS_STR 72
#define AS_SZ  (BM * AS_STR)
#define BS_SZ  (BK * BS_STR)
#define STG_FL (AS_SZ + BS_SZ)      // 4608 floats
#define STG_BY (STG_FL * 4)         // 18432 bytes
#define NSTAGE 3
#define GEMM_SMEM (NSTAGE * STG_BY) // 55296

template <int RELU>
__global__ __launch_bounds__(256, 2)
void gemm_tc(const float* __restrict__ A, const float* __restrict__ Wmat,
             const float* __restrict__ bias, float* __restrict__ Cout, int K)
{
    extern __shared__ float sm[];
    const int T = K / BK;

    const int tid  = threadIdx.x;
    const int wid  = tid >> 5;
    const int lane = tid & 31;
    const int lq   = lane & 3;
    const int l4   = lane >> 2;

    const int m0 = blockIdx.y * BM;
    const int n0 = blockIdx.x * BN;
    const int wm = (wid & 3) * 16;
    const int wn = (wid >> 2) * 32;

    const int ar0 = tid >> 3, ac = tid & 7;
    const int br0 = tid >> 4, bc = tid & 15;

    const uint32_t smBase = smem_u32(sm);
    const uint32_t aD0 = smBase + (uint32_t)(ar0 * AS_STR + ac * 4) * 4;
    const uint32_t aD1 = smBase + (uint32_t)((ar0 + 32) * AS_STR + ac * 4) * 4;
    const uint32_t bD0 = smBase + (uint32_t)(AS_SZ + br0 * BS_STR + bc * 4) * 4;
    const uint32_t bD1 = smBase + (uint32_t)(AS_SZ + (br0 + 16) * BS_STR + bc * 4) * 4;

    const float* aS0 = &A[(size_t)(m0 + ar0) * K + ac * 4];
    const float* aS1 = &A[(size_t)(m0 + ar0 + 32) * K + ac * 4];
    const float* bS0 = &Wmat[(size_t)br0 * DOUT + n0 + bc * 4];
    const float* bS1 = &Wmat[(size_t)(br0 + 16) * DOUT + n0 + bc * 4];

    auto issue = [&](int s) {
        const uint32_t off = (uint32_t)s * STG_BY;
        CP16(aD0 + off, aS0);
        CP16(aD1 + off, aS1);
        CP16(bD0 + off, bS0);
        CP16(bD1 + off, bS1);
        aS0 += BK; aS1 += BK;
        bS0 += (size_t)BK * DOUT; bS1 += (size_t)BK * DOUT;
    };

    float acc[4][4];
    #pragma unroll
    for (int nj = 0; nj < 4; nj++)
        #pragma unroll
        for (int r = 0; r < 4; r++) acc[nj][r] = 0.f;

    issue(0); CP_COMMIT();
    issue(1); CP_COMMIT();

    int buf = 0, sNext = 2;

    for (int t = 0; t < T; t++) {
        asm volatile("cp.async.wait_group 1;" ::: "memory");
        __syncthreads();

        if (t + 2 < T) issue(sNext);
        CP_COMMIT();    // exactly one group per iteration

        const float* Ab = sm + buf * STG_FL;
        const float* Bb = Ab + AS_SZ;

        #pragma unroll
        for (int k8 = 0; k8 < BK; k8 += 8) {
            const int R = wm + l4;
            uint32_t a0 = __float_as_uint(Ab[R * AS_STR + k8 + lq]);
            uint32_t a1 = __float_as_uint(Ab[(R + 8) * AS_STR + k8 + lq]);
            uint32_t a2 = __float_as_uint(Ab[R * AS_STR + k8 + lq + 4]);
            uint32_t a3 = __float_as_uint(Ab[(R + 8) * AS_STR + k8 + lq + 4]);
            uint32_t b[4][2];
            #pragma unroll
            for (int nj = 0; nj < 4; nj++) {
                const int Cn = wn + nj * 8 + l4;
                b[nj][0] = __float_as_uint(Bb[(k8 + lq) * BS_STR + Cn]);
                b[nj][1] = __float_as_uint(Bb[(k8 + lq + 4) * BS_STR + Cn]);
            }
            #pragma unroll
            for (int nj = 0; nj < 4; nj++)
                mma_tf32(acc[nj][0], acc[nj][1], acc[nj][2], acc[nj][3],
                         a0, a1, a2, a3, b[nj][0], b[nj][1]);
        }

        buf   = (buf == NSTAGE - 1) ? 0 : buf + 1;
        sNext = (sNext == NSTAGE - 1) ? 0 : sNext + 1;
    }

    #pragma unroll
    for (int nj = 0; nj < 4; nj++) {
        const int col = n0 + wn + nj * 8 + lq * 2;
        const float bb0 = bias[col];
        const float bb1 = bias[col + 1];
        const int row = m0 + wm + l4;
        float o0 = acc[nj][0] + bb0;
        float o1 = acc[nj][1] + bb1;
        float o2 = acc[nj][2] + bb0;
        float o3 = acc[nj][3] + bb1;
        if (RELU) {
            o0 = fmaxf(o0, 0.f); o1 = fmaxf(o1, 0.f);
            o2 = fmaxf(o2, 0.f); o3 = fmaxf(o3, 0.f);
        }
        float2 p0 = {o0, o1};
        float2 p1 = {o2, o3};
        *reinterpret_cast<float2*>(&Cout[(size_t)row * DOUT + col])       = p0;
        *reinterpret_cast<float2*>(&Cout[(size_t)(row + 8) * DOUT + col]) = p1;
    }
}

// ---------------------------------------------------------------------------
// Scores split-k x4: partial[q][b][l] = sum_{d in quarter q} relu(label-emb)^2
// grid (128, 4): x = 8-row b-group, y = k-quarter (256 k each).
// 256 threads: l=tid&127, bg=tid>>7 -> 4 b-rows. cp.async double-buffered
// 64-wide chunks, float4 compute, Ls stride 68 (17xf4, conflict-free .128).
// ---------------------------------------------------------------------------
#define LS_STR 68
#define SC_STG (NLAB * LS_STR + 8 * LS_STR)     // 9248 floats
#define SC_SMEM (2 * SC_STG * 4)                // 73984 bytes
#define NCHUNK_Q ((DOUT / KSPLIT) / 64)         // 4

__global__ __launch_bounds__(256)
void scores_part_kernel(const float* __restrict__ labels,
                        const float* __restrict__ emb,
                        float* __restrict__ part)
{
    extern __shared__ float sm[];
    const int tid = threadIdx.x;
    const int b0  = blockIdx.x * 8;
    const int kh  = blockIdx.y * (DOUT / KSPLIT);
    const int l   = tid & 127;
    const int bg  = tid >> 7;

    const uint32_t smBase = smem_u32(sm);
    const int lr = tid >> 4, lc = tid & 15;

    auto issue = [&](int c, int buf) {
        const int k0 = kh + c * 64;
        const uint32_t off = (uint32_t)buf * (SC_STG * 4);
        #pragma unroll
        for (int j = 0; j < 8; j++) {
            const int row = lr + j * 16;
            CP16(smBase + off + (uint32_t)(row * LS_STR + lc * 4) * 4,
                 &labels[(size_t)row * DOUT + k0 + lc * 4]);
        }
        if (tid < 128) {
            const int row = tid >> 4, c4 = tid & 15;
            CP16(smBase + off + (uint32_t)(NLAB * LS_STR + row * LS_STR + c4 * 4) * 4,
                 &emb[(size_t)(b0 + row) * DOUT + k0 + c4 * 4]);
        }
    };

    float acc0 = 0.f, acc1 = 0.f, acc2 = 0.f, acc3 = 0.f;

    issue(0, 0); CP_COMMIT();

    for (int c = 0; c < NCHUNK_Q; c++) {
        const int buf = c & 1;
        if (c + 1 < NCHUNK_Q) { issue(c + 1, buf ^ 1); }
        CP_COMMIT();
        asm volatile("cp.async.wait_group 1;" ::: "memory");
        __syncthreads();

        const float* Sb = sm + buf * SC_STG;
        const float4* Lp = reinterpret_cast<const float4*>(Sb + l * LS_STR);
        const float* Ep = Sb + NLAB * LS_STR + (bg * 4) * LS_STR;

        #pragma unroll
        for (int k4 = 0; k4 < 16; k4++) {
            const float4 lv = Lp[k4];
            const float4 e0 = *reinterpret_cast<const float4*>(Ep + 0 * LS_STR + k4 * 4);
            const float4 e1 = *reinterpret_cast<const float4*>(Ep + 1 * LS_STR + k4 * 4);
            const float4 e2 = *reinterpret_cast<const float4*>(Ep + 2 * LS_STR + k4 * 4);
            const float4 e3 = *reinterpret_cast<const float4*>(Ep + 3 * LS_STR + k4 * 4);
            float d;
            d = fmaxf(lv.x - e0.x, 0.f); acc0 = fmaf(d, d, acc0);
            d = fmaxf(lv.y - e0.y, 0.f); acc0 = fmaf(d, d, acc0);
            d = fmaxf(lv.z - e0.z, 0.f); acc0 = fmaf(d, d, acc0);
            d = fmaxf(lv.w - e0.w, 0.f); acc0 = fmaf(d, d, acc0);
            d = fmaxf(lv.x - e1.x, 0.f); acc1 = fmaf(d, d, acc1);
            d = fmaxf(lv.y - e1.y, 0.f); acc1 = fmaf(d, d, acc1);
            d = fmaxf(lv.z - e1.z, 0.f); acc1 = fmaf(d, d, acc1);
            d = fmaxf(lv.w - e1.w, 0.f); acc1 = fmaf(d, d, acc1);
            d = fmaxf(lv.x - e2.x, 0.f); acc2 = fmaf(d, d, acc2);
            d = fmaxf(lv.y - e2.y, 0.f); acc2 = fmaf(d, d, acc2);
            d = fmaxf(lv.z - e2.z, 0.f); acc2 = fmaf(d, d, acc2);
            d = fmaxf(lv.w - e2.w, 0.f); acc2 = fmaf(d, d, acc2);
            d = fmaxf(lv.x - e3.x, 0.f); acc3 = fmaf(d, d, acc3);
            d = fmaxf(lv.y - e3.y, 0.f); acc3 = fmaf(d, d, acc3);
            d = fmaxf(lv.z - e3.z, 0.f); acc3 = fmaf(d, d, acc3);
            d = fmaxf(lv.w - e3.w, 0.f); acc3 = fmaf(d, d, acc3);
        }
        __syncthreads();
    }

    float* dst = part + (size_t)blockIdx.y * (B_SZ * NLAB);
    dst[(size_t)(b0 + bg * 4 + 0) * NLAB + l] = acc0;
    dst[(size_t)(b0 + bg * 4 + 1) * NLAB + l] = acc1;
    dst[(size_t)(b0 + bg * 4 + 2) * NLAB + l] = acc2;
    dst[(size_t)(b0 + bg * 4 + 3) * NLAB + l] = acc3;
}

__global__ __launch_bounds__(256)
void scores_reduce_kernel(const float* __restrict__ part, float* __restrict__ out)
{
    const int idx = blockIdx.x * 256 + threadIdx.x;   // 0 .. 131071
    float s = part[idx]
            + part[1 * B_SZ * NLAB + idx]
            + part[2 * B_SZ * NLAB + idx]
            + part[3 * B_SZ * NLAB + idx];
    out[idx] = -sqrtf(s);
}

// ---------------------------------------------------------------------------
// Launch
// ---------------------------------------------------------------------------
extern "C" void kernel_launch(void* const* d_in, const int* in_sizes, int n_in,
                              void* d_out, int out_size)
{
    const float* sbj    = (const float*)d_in[0];
    const float* obj    = (const float*)d_in[1];
    const float* W1     = (const float*)d_in[2];
    const float* b1     = (const float*)d_in[3];
    const float* W2     = (const float*)d_in[4];
    const float* b2     = (const float*)d_in[5];
    const float* labels = (const float*)d_in[6];
    float* out = (float*)d_out;

    float *x_ptr, *hidden_ptr, *emb_ptr, *part_ptr;
    cudaGetSymbolAddress((void**)&x_ptr, g_x);
    cudaGetSymbolAddress((void**)&hidden_ptr, g_hidden);
    cudaGetSymbolAddress((void**)&emb_ptr, g_emb);
    cudaGetSymbolAddress((void**)&part_ptr, g_part);

    cudaFuncSetAttribute(gemm_tc<1>, cudaFuncAttributeMaxDynamicSharedMemorySize, GEMM_SMEM);
    cudaFuncSetAttribute(gemm_tc<0>, cudaFuncAttributeMaxDynamicSharedMemorySize, GEMM_SMEM);
    cudaFuncSetAttribute(scores_part_kernel, cudaFuncAttributeMaxDynamicSharedMemorySize, SC_SMEM);

    relu_cat_kernel<<<(B_SZ * DIN / 4) / 256, 256>>>(sbj, obj, x_ptr);

    dim3 grid(DOUT / BN, B_SZ / BM);   // (16,16) = 256 CTAs
    gemm_tc<1><<<grid, 256, GEMM_SMEM>>>(x_ptr, W1, b1, hidden_ptr, DIN);
    gemm_tc<0><<<grid, 256, GEMM_SMEM>>>(hidden_ptr, W2, b2, emb_ptr, DOUT);

    scores_part_kernel<<<dim3(B_SZ / 8, KSPLIT), 256, SC_SMEM>>>(labels, emb_ptr, part_ptr);
    scores_reduce_kernel<<<(B_SZ * NLAB) / 256, 256>>>(part_ptr, out);
}

// round 9
// speedup vs baseline: 2.4506x; 1.0017x over previous
#include <cuda_runtime.h>
#include <cstdint>

#define B_SZ  1024
#define DHALF 2048
#define DIN   4096
#define DOUT  1024
#define NLAB  128
#define KSPLIT 4

// Scratch (allocation-free rule: __device__ globals)
__device__ float g_x[B_SZ * DIN];               // relu(concat(sbj,obj))
__device__ float g_hidden[B_SZ * DOUT];         // relu(hidden)
__device__ float g_emb[B_SZ * DOUT];            // emb
__device__ float g_part[KSPLIT * B_SZ * NLAB];  // scores split-k partials

// ---------------------------------------------------------------------------
// helpers
// ---------------------------------------------------------------------------
__device__ __forceinline__ uint32_t smem_u32(const void* p) {
    uint32_t a;
    asm("{ .reg .u64 t; cvta.to.shared.u64 t, %1; cvt.u32.u64 %0, t; }"
        : "=r"(a) : "l"(p));
    return a;
}
#define CP16(dst, src) asm volatile("cp.async.cg.shared.global [%0], [%1], 16;" :: "r"(dst), "l"(src) : "memory")
#define CP_COMMIT()    asm volatile("cp.async.commit_group;" ::: "memory")

__device__ __forceinline__ void mma_tf32(float& c0, float& c1, float& c2, float& c3,
                                         uint32_t a0, uint32_t a1, uint32_t a2, uint32_t a3,
                                         uint32_t b0, uint32_t b1) {
    asm volatile(
        "mma.sync.aligned.m16n8k8.row.col.f32.tf32.tf32.f32 "
        "{%0,%1,%2,%3}, {%4,%5,%6,%7}, {%8,%9}, {%0,%1,%2,%3};"
        : "+f"(c0), "+f"(c1), "+f"(c2), "+f"(c3)
        : "r"(a0), "r"(a1), "r"(a2), "r"(a3), "r"(b0), "r"(b1));
}

// ---------------------------------------------------------------------------
// Prepass: g_x[m][k] = relu(concat(sbj,obj))
// ---------------------------------------------------------------------------
__global__ __launch_bounds__(256)
void relu_cat_kernel(const float* __restrict__ sbj, const float* __restrict__ obj,
                     float* __restrict__ x)
{
    const int idx = blockIdx.x * 256 + threadIdx.x;
    const int row = idx >> 10;
    const int c4  = idx & 1023;
    const int col = c4 * 4;
    const float* src = (col < DHALF) ? &sbj[(size_t)row * DHALF + col]
                                     : &obj[(size_t)row * DHALF + col - DHALF];
    float4 v = *reinterpret_cast<const float4*>(src);
    v.x = fmaxf(v.x, 0.f); v.y = fmaxf(v.y, 0.f);
    v.z = fmaxf(v.z, 0.f); v.w = fmaxf(v.w, 0.f);
    *reinterpret_cast<float4*>(&x[(size_t)row * DIN + col]) = v;
}

// ---------------------------------------------------------------------------
// tf32 tensor GEMM (R5 measured-best config): C = act(A @ W + bias)
// BM=BN=64, BK=32, 8 warps (4m x 2n), warp tile 16x32.
// 3-stage cp.async ring, ONE __syncthreads per stage:
//   iter t: wait_group 1 -> sync -> issue(t+2) -> commit -> mma(t)
// Bank-clean: As stride 36 (4*l4+lq perm), Bs stride 72 (8*lq+l4 perm).
// ---------------------------------------------------------------------------
#define BM 64
#define BN 64
#define BK 32
#define AS_STR 36
#define BS_STR 72
#define AS_SZ  (BM * AS_STR)
#define BS_SZ  (BK * BS_STR)
#define STG_FL (AS_SZ + BS_SZ)      // 4608 floats
#define STG_BY (STG_FL * 4)         // 18432 bytes
#define NSTAGE 3
#define GEMM_SMEM (NSTAGE * STG_BY) // 55296

template <int RELU>
__global__ __launch_bounds__(256, 2)
void gemm_tc(const float* __restrict__ A, const float* __restrict__ Wmat,
             const float* __restrict__ bias, float* __restrict__ Cout, int K)
{
    extern __shared__ float sm[];
    const int T = K / BK;

    const int tid  = threadIdx.x;
    const int wid  = tid >> 5;
    const int lane = tid & 31;
    const int lq   = lane & 3;
    const int l4   = lane >> 2;

    const int m0 = blockIdx.y * BM;
    const int n0 = blockIdx.x * BN;
    const int wm = (wid & 3) * 16;
    const int wn = (wid >> 2) * 32;

    const int ar0 = tid >> 3, ac = tid & 7;
    const int br0 = tid >> 4, bc = tid & 15;

    const uint32_t smBase = smem_u32(sm);
    const uint32_t aD0 = smBase + (uint32_t)(ar0 * AS_STR + ac * 4) * 4;
    const uint32_t aD1 = smBase + (uint32_t)((ar0 + 32) * AS_STR + ac * 4) * 4;
    const uint32_t bD0 = smBase + (uint32_t)(AS_SZ + br0 * BS_STR + bc * 4) * 4;
    const uint32_t bD1 = smBase + (uint32_t)(AS_SZ + (br0 + 16) * BS_STR + bc * 4) * 4;

    const float* aS0 = &A[(size_t)(m0 + ar0) * K + ac * 4];
    const float* aS1 = &A[(size_t)(m0 + ar0 + 32) * K + ac * 4];
    const float* bS0 = &Wmat[(size_t)br0 * DOUT + n0 + bc * 4];
    const float* bS1 = &Wmat[(size_t)(br0 + 16) * DOUT + n0 + bc * 4];

    auto issue = [&](int s) {
        const uint32_t off = (uint32_t)s * STG_BY;
        CP16(aD0 + off, aS0);
        CP16(aD1 + off, aS1);
        CP16(bD0 + off, bS0);
        CP16(bD1 + off, bS1);
        aS0 += BK; aS1 += BK;
        bS0 += (size_t)BK * DOUT; bS1 += (size_t)BK * DOUT;
    };

    float acc[4][4];
    #pragma unroll
    for (int nj = 0; nj < 4; nj++)
        #pragma unroll
        for (int r = 0; r < 4; r++) acc[nj][r] = 0.f;

    issue(0); CP_COMMIT();
    issue(1); CP_COMMIT();

    int buf = 0, sNext = 2;

    for (int t = 0; t < T; t++) {
        asm volatile("cp.async.wait_group 1;" ::: "memory");
        __syncthreads();

        if (t + 2 < T) issue(sNext);
        CP_COMMIT();    // exactly one group per iteration

        const float* Ab = sm + buf * STG_FL;
        const float* Bb = Ab + AS_SZ;

        #pragma unroll
        for (int k8 = 0; k8 < BK; k8 += 8) {
            const int R = wm + l4;
            uint32_t a0 = __float_as_uint(Ab[R * AS_STR + k8 + lq]);
            uint32_t a1 = __float_as_uint(Ab[(R + 8) * AS_STR + k8 + lq]);
            uint32_t a2 = __float_as_uint(Ab[R * AS_STR + k8 + lq + 4]);
            uint32_t a3 = __float_as_uint(Ab[(R + 8) * AS_STR + k8 + lq + 4]);
            uint32_t b[4][2];
            #pragma unroll
            for (int nj = 0; nj < 4; nj++) {
                const int Cn = wn + nj * 8 + l4;
                b[nj][0] = __float_as_uint(Bb[(k8 + lq) * BS_STR + Cn]);
                b[nj][1] = __float_as_uint(Bb[(k8 + lq + 4) * BS_STR + Cn]);
            }
            #pragma unroll
            for (int nj = 0; nj < 4; nj++)
                mma_tf32(acc[nj][0], acc[nj][1], acc[nj][2], acc[nj][3],
                         a0, a1, a2, a3, b[nj][0], b[nj][1]);
        }

        buf   = (buf == NSTAGE - 1) ? 0 : buf + 1;
        sNext = (sNext == NSTAGE - 1) ? 0 : sNext + 1;
    }

    #pragma unroll
    for (int nj = 0; nj < 4; nj++) {
        const int col = n0 + wn + nj * 8 + lq * 2;
        const float bb0 = bias[col];
        const float bb1 = bias[col + 1];
        const int row = m0 + wm + l4;
        float o0 = acc[nj][0] + bb0;
        float o1 = acc[nj][1] + bb1;
        float o2 = acc[nj][2] + bb0;
        float o3 = acc[nj][3] + bb1;
        if (RELU) {
            o0 = fmaxf(o0, 0.f); o1 = fmaxf(o1, 0.f);
            o2 = fmaxf(o2, 0.f); o3 = fmaxf(o3, 0.f);
        }
        float2 p0 = {o0, o1};
        float2 p1 = {o2, o3};
        *reinterpret_cast<float2*>(&Cout[(size_t)row * DOUT + col])       = p0;
        *reinterpret_cast<float2*>(&Cout[(size_t)(row + 8) * DOUT + col]) = p1;
    }
}

// ---------------------------------------------------------------------------
// Scores split-k x4: partial[q][b][l] = sum_{d in quarter q} relu(label-emb)^2
// grid (128, 4): x = 8-row b-group, y = k-quarter (256 k each).
// 256 threads: l=tid&127, bg=tid>>7 -> 4 b-rows. cp.async double-buffered
// 64-wide chunks, float4 compute, Ls stride 68 (17xf4, conflict-free .128).
// ---------------------------------------------------------------------------
#define LS_STR 68
#define SC_STG (NLAB * LS_STR + 8 * LS_STR)     // 9248 floats
#define SC_SMEM (2 * SC_STG * 4)                // 73984 bytes
#define NCHUNK_Q ((DOUT / KSPLIT) / 64)         // 4

__global__ __launch_bounds__(256)
void scores_part_kernel(const float* __restrict__ labels,
                        const float* __restrict__ emb,
                        float* __restrict__ part)
{
    extern __shared__ float sm[];
    const int tid = threadIdx.x;
    const int b0  = blockIdx.x * 8;
    const int kh  = blockIdx.y * (DOUT / KSPLIT);
    const int l   = tid & 127;
    const int bg  = tid >> 7;

    const uint32_t smBase = smem_u32(sm);
    const int lr = tid >> 4, lc = tid & 15;

    auto issue = [&](int c, int buf) {
        const int k0 = kh + c * 64;
        const uint32_t off = (uint32_t)buf * (SC_STG * 4);
        #pragma unroll
        for (int j = 0; j < 8; j++) {
            const int row = lr + j * 16;
            CP16(smBase + off + (uint32_t)(row * LS_STR + lc * 4) * 4,
                 &labels[(size_t)row * DOUT + k0 + lc * 4]);
        }
        if (tid < 128) {
            const int row = tid >> 4, c4 = tid & 15;
            CP16(smBase + off + (uint32_t)(NLAB * LS_STR + row * LS_STR + c4 * 4) * 4,
                 &emb[(size_t)(b0 + row) * DOUT + k0 + c4 * 4]);
        }
    };

    float acc0 = 0.f, acc1 = 0.f, acc2 = 0.f, acc3 = 0.f;

    issue(0, 0); CP_COMMIT();

    for (int c = 0; c < NCHUNK_Q; c++) {
        const int buf = c & 1;
        if (c + 1 < NCHUNK_Q) { issue(c + 1, buf ^ 1); }
        CP_COMMIT();
        asm volatile("cp.async.wait_group 1;" ::: "memory");
        __syncthreads();

        const float* Sb = sm + buf * SC_STG;
        const float4* Lp = reinterpret_cast<const float4*>(Sb + l * LS_STR);
        const float* Ep = Sb + NLAB * LS_STR + (bg * 4) * LS_STR;

        #pragma unroll
        for (int k4 = 0; k4 < 16; k4++) {
            const float4 lv = Lp[k4];
            const float4 e0 = *reinterpret_cast<const float4*>(Ep + 0 * LS_STR + k4 * 4);
            const float4 e1 = *reinterpret_cast<const float4*>(Ep + 1 * LS_STR + k4 * 4);
            const float4 e2 = *reinterpret_cast<const float4*>(Ep + 2 * LS_STR + k4 * 4);
            const float4 e3 = *reinterpret_cast<const float4*>(Ep + 3 * LS_STR + k4 * 4);
            float d;
            d = fmaxf(lv.x - e0.x, 0.f); acc0 = fmaf(d, d, acc0);
            d = fmaxf(lv.y - e0.y, 0.f); acc0 = fmaf(d, d, acc0);
            d = fmaxf(lv.z - e0.z, 0.f); acc0 = fmaf(d, d, acc0);
            d = fmaxf(lv.w - e0.w, 0.f); acc0 = fmaf(d, d, acc0);
            d = fmaxf(lv.x - e1.x, 0.f); acc1 = fmaf(d, d, acc1);
            d = fmaxf(lv.y - e1.y, 0.f); acc1 = fmaf(d, d, acc1);
            d = fmaxf(lv.z - e1.z, 0.f); acc1 = fmaf(d, d, acc1);
            d = fmaxf(lv.w - e1.w, 0.f); acc1 = fmaf(d, d, acc1);
            d = fmaxf(lv.x - e2.x, 0.f); acc2 = fmaf(d, d, acc2);
            d = fmaxf(lv.y - e2.y, 0.f); acc2 = fmaf(d, d, acc2);
            d = fmaxf(lv.z - e2.z, 0.f); acc2 = fmaf(d, d, acc2);
            d = fmaxf(lv.w - e2.w, 0.f); acc2 = fmaf(d, d, acc2);
            d = fmaxf(lv.x - e3.x, 0.f); acc3 = fmaf(d, d, acc3);
            d = fmaxf(lv.y - e3.y, 0.f); acc3 = fmaf(d, d, acc3);
            d = fmaxf(lv.z - e3.z, 0.f); acc3 = fmaf(d, d, acc3);
            d = fmaxf(lv.w - e3.w, 0.f); acc3 = fmaf(d, d, acc3);
        }
        __syncthreads();
    }

    float* dst = part + (size_t)blockIdx.y * (B_SZ * NLAB);
    dst[(size_t)(b0 + bg * 4 + 0) * NLAB + l] = acc0;
    dst[(size_t)(b0 + bg * 4 + 1) * NLAB + l] = acc1;
    dst[(size_t)(b0 + bg * 4 + 2) * NLAB + l] = acc2;
    dst[(size_t)(b0 + bg * 4 + 3) * NLAB + l] = acc3;
}

__global__ __launch_bounds__(256)
void scores_reduce_kernel(const float* __restrict__ part, float* __restrict__ out)
{
    const int idx = blockIdx.x * 256 + threadIdx.x;   // 0 .. 131071
    float s = part[idx]
            + part[1 * B_SZ * NLAB + idx]
            + part[2 * B_SZ * NLAB + idx]
            + part[3 * B_SZ * NLAB + idx];
    out[idx] = -sqrtf(s);
}

// ---------------------------------------------------------------------------
// Launch
// ---------------------------------------------------------------------------
extern "C" void kernel_launch(void* const* d_in, const int* in_sizes, int n_in,
                              void* d_out, int out_size)
{
    const float* sbj    = (const float*)d_in[0];
    const float* obj    = (const float*)d_in[1];
    const float* W1     = (const float*)d_in[2];
    const float* b1     = (const float*)d_in[3];
    const float* W2     = (const float*)d_in[4];
    const float* b2     = (const float*)d_in[5];
    const float* labels = (const float*)d_in[6];
    float* out = (float*)d_out;

    float *x_ptr, *hidden_ptr, *emb_ptr, *part_ptr;
    cudaGetSymbolAddress((void**)&x_ptr, g_x);
    cudaGetSymbolAddress((void**)&hidden_ptr, g_hidden);
    cudaGetSymbolAddress((void**)&emb_ptr, g_emb);
    cudaGetSymbolAddress((void**)&part_ptr, g_part);

    cudaFuncSetAttribute(gemm_tc<1>, cudaFuncAttributeMaxDynamicSharedMemorySize, GEMM_SMEM);
    cudaFuncSetAttribute(gemm_tc<0>, cudaFuncAttributeMaxDynamicSharedMemorySize, GEMM_SMEM);
    cudaFuncSetAttribute(scores_part_kernel, cudaFuncAttributeMaxDynamicSharedMemorySize, SC_SMEM);

    relu_cat_kernel<<<(B_SZ * DIN / 4) / 256, 256>>>(sbj, obj, x_ptr);

    dim3 grid(DOUT / BN, B_SZ / BM);   // (16,16) = 256 CTAs
    gemm_tc<1><<<grid, 256, GEMM_SMEM>>>(x_ptr, W1, b1, hidden_ptr, DIN);
    gemm_tc<0><<<grid, 256, GEMM_SMEM>>>(hidden_ptr, W2, b2, emb_ptr, DOUT);

    scores_part_kernel<<<dim3(B_SZ / 8, KSPLIT), 256, SC_SMEM>>>(labels, emb_ptr, part_ptr);
    scores_reduce_kernel<<<(B_SZ * NLAB) / 256, 256>>>(part_ptr, out);
}

// round 10
// speedup vs baseline: 2.4522x; 1.0006x over previous
#include <cuda_runtime.h>
#include <cstdint>

#define B_SZ  1024
#define DHALF 2048
#define DIN   4096
#define DOUT  1024
#define NLAB  128
#define KSPLIT 4

// Scratch (allocation-free rule: __device__ globals)
__device__ float g_x[B_SZ * DIN];               // relu(concat(sbj,obj))
__device__ float g_hidden[B_SZ * DOUT];         // relu(hidden)
__device__ float g_emb[B_SZ * DOUT];            // emb
__device__ float g_part[KSPLIT * B_SZ * NLAB];  // scores split-k partials

// ---------------------------------------------------------------------------
// helpers
// ---------------------------------------------------------------------------
__device__ __forceinline__ uint32_t smem_u32(const void* p) {
    uint32_t a;
    asm("{ .reg .u64 t; cvta.to.shared.u64 t, %1; cvt.u32.u64 %0, t; }"
        : "=r"(a) : "l"(p));
    return a;
}
#define CP16(dst, src) asm volatile("cp.async.cg.shared.global [%0], [%1], 16;" :: "r"(dst), "l"(src) : "memory")
#define CP_COMMIT()    asm volatile("cp.async.commit_group;" ::: "memory")

__device__ __forceinline__ void mma_tf32(float& c0, float& c1, float& c2, float& c3,
                                         uint32_t a0, uint32_t a1, uint32_t a2, uint32_t a3,
                                         uint32_t b0, uint32_t b1) {
    asm volatile(
        "mma.sync.aligned.m16n8k8.row.col.f32.tf32.tf32.f32 "
        "{%0,%1,%2,%3}, {%4,%5,%6,%7}, {%8,%9}, {%0,%1,%2,%3};"
        : "+f"(c0), "+f"(c1), "+f"(c2), "+f"(c3)
        : "r"(a0), "r"(a1), "r"(a2), "r"(a3), "r"(b0), "r"(b1));
}

// ---------------------------------------------------------------------------
// Prepass: g_x[m][k] = relu(concat(sbj,obj))
// ---------------------------------------------------------------------------
__global__ __launch_bounds__(256)
void relu_cat_kernel(const float* __restrict__ sbj, const float* __restrict__ obj,
                     float* __restrict__ x)
{
    const int idx = blockIdx.x * 256 + threadIdx.x;
    const int row = idx >> 10;
    const int c4  = idx & 1023;
    const int col = c4 * 4;
    const float* src = (col < DHALF) ? &sbj[(size_t)row * DHALF + col]
                                     : &obj[(size_t)row * DHALF + col - DHALF];
    float4 v = *reinterpret_cast<const float4*>(src);
    v.x = fmaxf(v.x, 0.f); v.y = fmaxf(v.y, 0.f);
    v.z = fmaxf(v.z, 0.f); v.w = fmaxf(v.w, 0.f);
    *reinterpret_cast<float4*>(&x[(size_t)row * DIN + col]) = v;
}

// ---------------------------------------------------------------------------
// tf32 tensor GEMM (R5 measured-best config): C = act(A @ W + bias)
// BM=BN=64, BK=32, 8 warps (4m x 2n), warp tile 16x32.
// 3-stage cp.async ring, ONE __syncthreads per stage:
//   iter t: wait_group 1 -> sync -> issue(t+2) -> commit -> mma(t)
// Bank-clean: As stride 36 (4*l4+lq perm), Bs stride 72 (8*lq+l4 perm).
// ---------------------------------------------------------------------------
#define BM 64
#define BN 64
#define BK 32
#define AS_STR 36
#define BS_STR 72
#define AS_SZ  (BM * AS_STR)
#define BS_SZ  (BK * BS_STR)
#define STG_FL (AS_SZ + BS_SZ)      // 4608 floats
#define STG_BY (STG_FL * 4)         // 18432 bytes
#define NSTAGE 3
#define GEMM_SMEM (NSTAGE * STG_BY) // 55296

template <int RELU>
__global__ __launch_bounds__(256, 2)
void gemm_tc(const float* __restrict__ A, const float* __restrict__ Wmat,
             const float* __restrict__ bias, float* __restrict__ Cout, int K)
{
    extern __shared__ float sm[];
    const int T = K / BK;

    const int tid  = threadIdx.x;
    const int wid  = tid >> 5;
    const int lane = tid & 31;
    const int lq   = lane & 3;
    const int l4   = lane >> 2;

    const int m0 = blockIdx.y * BM;
    const int n0 = blockIdx.x * BN;
    const int wm = (wid & 3) * 16;
    const int wn = (wid >> 2) * 32;

    const int ar0 = tid >> 3, ac = tid & 7;
    const int br0 = tid >> 4, bc = tid & 15;

    const uint32_t smBase = smem_u32(sm);
    const uint32_t aD0 = smBase + (uint32_t)(ar0 * AS_STR + ac * 4) * 4;
    const uint32_t aD1 = smBase + (uint32_t)((ar0 + 32) * AS_STR + ac * 4) * 4;
    const uint32_t bD0 = smBase + (uint32_t)(AS_SZ + br0 * BS_STR + bc * 4) * 4;
    const uint32_t bD1 = smBase + (uint32_t)(AS_SZ + (br0 + 16) * BS_STR + bc * 4) * 4;

    const float* aS0 = &A[(size_t)(m0 + ar0) * K + ac * 4];
    const float* aS1 = &A[(size_t)(m0 + ar0 + 32) * K + ac * 4];
    const float* bS0 = &Wmat[(size_t)br0 * DOUT + n0 + bc * 4];
    const float* bS1 = &Wmat[(size_t)(br0 + 16) * DOUT + n0 + bc * 4];

    auto issue = [&](int s) {
        const uint32_t off = (uint32_t)s * STG_BY;
        CP16(aD0 + off, aS0);
        CP16(aD1 + off, aS1);
        CP16(bD0 + off, bS0);
        CP16(bD1 + off, bS1);
        aS0 += BK; aS1 += BK;
        bS0 += (size_t)BK * DOUT; bS1 += (size_t)BK * DOUT;
    };

    float acc[4][4];
    #pragma unroll
    for (int nj = 0; nj < 4; nj++)
        #pragma unroll
        for (int r = 0; r < 4; r++) acc[nj][r] = 0.f;

    issue(0); CP_COMMIT();
    issue(1); CP_COMMIT();

    int buf = 0, sNext = 2;

    for (int t = 0; t < T; t++) {
        asm volatile("cp.async.wait_group 1;" ::: "memory");
        __syncthreads();

        if (t + 2 < T) issue(sNext);
        CP_COMMIT();    // exactly one group per iteration

        const float* Ab = sm + buf * STG_FL;
        const float* Bb = Ab + AS_SZ;

        #pragma unroll
        for (int k8 = 0; k8 < BK; k8 += 8) {
            const int R = wm + l4;
            uint32_t a0 = __float_as_uint(Ab[R * AS_STR + k8 + lq]);
            uint32_t a1 = __float_as_uint(Ab[(R + 8) * AS_STR + k8 + lq]);
            uint32_t a2 = __float_as_uint(Ab[R * AS_STR + k8 + lq + 4]);
            uint32_t a3 = __float_as_uint(Ab[(R + 8) * AS_STR + k8 + lq + 4]);
            uint32_t b[4][2];
            #pragma unroll
            for (int nj = 0; nj < 4; nj++) {
                const int Cn = wn + nj * 8 + l4;
                b[nj][0] = __float_as_uint(Bb[(k8 + lq) * BS_STR + Cn]);
                b[nj][1] = __float_as_uint(Bb[(k8 + lq + 4) * BS_STR + Cn]);
            }
            #pragma unroll
            for (int nj = 0; nj < 4; nj++)
                mma_tf32(acc[nj][0], acc[nj][1], acc[nj][2], acc[nj][3],
                         a0, a1, a2, a3, b[nj][0], b[nj][1]);
        }

        buf   = (buf == NSTAGE - 1) ? 0 : buf + 1;
        sNext = (sNext == NSTAGE - 1) ? 0 : sNext + 1;
    }

    #pragma unroll
    for (int nj = 0; nj < 4; nj++) {
        const int col = n0 + wn + nj * 8 + lq * 2;
        const float bb0 = bias[col];
        const float bb1 = bias[col + 1];
        const int row = m0 + wm + l4;
        float o0 = acc[nj][0] + bb0;
        float o1 = acc[nj][1] + bb1;
        float o2 = acc[nj][2] + bb0;
        float o3 = acc[nj][3] + bb1;
        if (RELU) {
            o0 = fmaxf(o0, 0.f); o1 = fmaxf(o1, 0.f);
            o2 = fmaxf(o2, 0.f); o3 = fmaxf(o3, 0.f);
        }
        float2 p0 = {o0, o1};
        float2 p1 = {o2, o3};
        *reinterpret_cast<float2*>(&Cout[(size_t)row * DOUT + col])       = p0;
        *reinterpret_cast<float2*>(&Cout[(size_t)(row + 8) * DOUT + col]) = p1;
    }
}

// ---------------------------------------------------------------------------
// Scores split-k x4: partial[q][b][l] = sum_{d in quarter q} relu(label-emb)^2
// grid (128, 4): x = 8-row b-group, y = k-quarter (256 k each).
// 256 threads: l=tid&127, bg=tid>>7 -> 4 b-rows. cp.async double-buffered
// 64-wide chunks, float4 compute, Ls stride 68 (17xf4, conflict-free .128).
// ---------------------------------------------------------------------------
#define LS_STR 68
#define SC_STG (NLAB * LS_STR + 8 * LS_STR)     // 9248 floats
#define SC_SMEM (2 * SC_STG * 4)                // 73984 bytes
#define NCHUNK_Q ((DOUT / KSPLIT) / 64)         // 4

__global__ __launch_bounds__(256)
void scores_part_kernel(const float* __restrict__ labels,
                        const float* __restrict__ emb,
                        float* __restrict__ part)
{
    extern __shared__ float sm[];
    const int tid = threadIdx.x;
    const int b0  = blockIdx.x * 8;
    const int kh  = blockIdx.y * (DOUT / KSPLIT);
    const int l   = tid & 127;
    const int bg  = tid >> 7;

    const uint32_t smBase = smem_u32(sm);
    const int lr = tid >> 4, lc = tid & 15;

    auto issue = [&](int c, int buf) {
        const int k0 = kh + c * 64;
        const uint32_t off = (uint32_t)buf * (SC_STG * 4);
        #pragma unroll
        for (int j = 0; j < 8; j++) {
            const int row = lr + j * 16;
            CP16(smBase + off + (uint32_t)(row * LS_STR + lc * 4) * 4,
                 &labels[(size_t)row * DOUT + k0 + lc * 4]);
        }
        if (tid < 128) {
            const int row = tid >> 4, c4 = tid & 15;
            CP16(smBase + off + (uint32_t)(NLAB * LS_STR + row * LS_STR + c4 * 4) * 4,
                 &emb[(size_t)(b0 + row) * DOUT + k0 + c4 * 4]);
        }
    };

    float acc0 = 0.f, acc1 = 0.f, acc2 = 0.f, acc3 = 0.f;

    issue(0, 0); CP_COMMIT();

    for (int c = 0; c < NCHUNK_Q; c++) {
        const int buf = c & 1;
        if (c + 1 < NCHUNK_Q) { issue(c + 1, buf ^ 1); }
        CP_COMMIT();
        asm volatile("cp.async.wait_group 1;" ::: "memory");
        __syncthreads();

        const float* Sb = sm + buf * SC_STG;
        const float4* Lp = reinterpret_cast<const float4*>(Sb + l * LS_STR);
        const float* Ep = Sb + NLAB * LS_STR + (bg * 4) * LS_STR;

        #pragma unroll
        for (int k4 = 0; k4 < 16; k4++) {
            const float4 lv = Lp[k4];
            const float4 e0 = *reinterpret_cast<const float4*>(Ep + 0 * LS_STR + k4 * 4);
            const float4 e1 = *reinterpret_cast<const float4*>(Ep + 1 * LS_STR + k4 * 4);
            const float4 e2 = *reinterpret_cast<const float4*>(Ep + 2 * LS_STR + k4 * 4);
            const float4 e3 = *reinterpret_cast<const float4*>(Ep + 3 * LS_STR + k4 * 4);
            float d;
            d = fmaxf(lv.x - e0.x, 0.f); acc0 = fmaf(d, d, acc0);
            d = fmaxf(lv.y - e0.y, 0.f); acc0 = fmaf(d, d, acc0);
            d = fmaxf(lv.z - e0.z, 0.f); acc0 = fmaf(d, d, acc0);
            d = fmaxf(lv.w - e0.w, 0.f); acc0 = fmaf(d, d, acc0);
            d = fmaxf(lv.x - e1.x, 0.f); acc1 = fmaf(d, d, acc1);
            d = fmaxf(lv.y - e1.y, 0.f); acc1 = fmaf(d, d, acc1);
            d = fmaxf(lv.z - e1.z, 0.f); acc1 = fmaf(d, d, acc1);
            d = fmaxf(lv.w - e1.w, 0.f); acc1 = fmaf(d, d, acc1);
            d = fmaxf(lv.x - e2.x, 0.f); acc2 = fmaf(d, d, acc2);
            d = fmaxf(lv.y - e2.y, 0.f); acc2 = fmaf(d, d, acc2);
            d = fmaxf(lv.z - e2.z, 0.f); acc2 = fmaf(d, d, acc2);
            d = fmaxf(lv.w - e2.w, 0.f); acc2 = fmaf(d, d, acc2);
            d = fmaxf(lv.x - e3.x, 0.f); acc3 = fmaf(d, d, acc3);
            d = fmaxf(lv.y - e3.y, 0.f); acc3 = fmaf(d, d, acc3);
            d = fmaxf(lv.z - e3.z, 0.f); acc3 = fmaf(d, d, acc3);
            d = fmaxf(lv.w - e3.w, 0.f); acc3 = fmaf(d, d, acc3);
        }
        __syncthreads();
    }

    float* dst = part + (size_t)blockIdx.y * (B_SZ * NLAB);
    dst[(size_t)(b0 + bg * 4 + 0) * NLAB + l] = acc0;
    dst[(size_t)(b0 + bg * 4 + 1) * NLAB + l] = acc1;
    dst[(size_t)(b0 + bg * 4 + 2) * NLAB + l] = acc2;
    dst[(size_t)(b0 + bg * 4 + 3) * NLAB + l] = acc3;
}

__global__ __launch_bounds__(256)
void scores_reduce_kernel(const float* __restrict__ part, float* __restrict__ out)
{
    const int idx = blockIdx.x * 256 + threadIdx.x;   // 0 .. 131071
    float s = part[idx]
            + part[1 * B_SZ * NLAB + idx]
            + part[2 * B_SZ * NLAB + idx]
            + part[3 * B_SZ * NLAB + idx];
    out[idx] = -sqrtf(s);
}

// ---------------------------------------------------------------------------
// Launch
// ---------------------------------------------------------------------------
extern "C" void kernel_launch(void* const* d_in, const int* in_sizes, int n_in,
                              void* d_out, int out_size)
{
    const float* sbj    = (const float*)d_in[0];
    const float* obj    = (const float*)d_in[1];
    const float* W1     = (const float*)d_in[2];
    const float* b1     = (const float*)d_in[3];
    const float* W2     = (const float*)d_in[4];
    const float* b2     = (const float*)d_in[5];
    const float* labels = (const float*)d_in[6];
    float* out = (float*)d_out;

    float *x_ptr, *hidden_ptr, *emb_ptr, *part_ptr;
    cudaGetSymbolAddress((void**)&x_ptr, g_x);
    cudaGetSymbolAddress((void**)&hidden_ptr, g_hidden);
    cudaGetSymbolAddress((void**)&emb_ptr, g_emb);
    cudaGetSymbolAddress((void**)&part_ptr, g_part);

    cudaFuncSetAttribute(gemm_tc<1>, cudaFuncAttributeMaxDynamicSharedMemorySize, GEMM_SMEM);
    cudaFuncSetAttribute(gemm_tc<0>, cudaFuncAttributeMaxDynamicSharedMemorySize, GEMM_SMEM);
    cudaFuncSetAttribute(scores_part_kernel, cudaFuncAttributeMaxDynamicSharedMemorySize, SC_SMEM);

    relu_cat_kernel<<<(B_SZ * DIN / 4) / 256, 256>>>(sbj, obj, x_ptr);

    dim3 grid(DOUT / BN, B_SZ / BM);   // (16,16) = 256 CTAs
    gemm_tc<1><<<grid, 256, GEMM_SMEM>>>(x_ptr, W1, b1, hidden_ptr, DIN);
    gemm_tc<0><<<grid, 256, GEMM_SMEM>>>(hidden_ptr, W2, b2, emb_ptr, DOUT);

    scores_part_kernel<<<dim3(B_SZ / 8, KSPLIT), 256, SC_SMEM>>>(labels, emb_ptr, part_ptr);
    scores_reduce_kernel<<<(B_SZ * NLAB) / 256, 256>>>(part_ptr, out);
}